// round 2
// baseline (speedup 1.0000x reference)
#include <cuda_runtime.h>
#include <math.h>

#define C_IN 256
#define HID  128
#define HW   196      // 14*14
#define PHW  49       // 7*7
#define MQ   25088    // 128 * 196
#define MK   6272     // 128 * 49
#define NQ_B 12544    // per-batch query count
#define NK_B 3136     // per-batch key count

// ---------------- scratch (device globals; no allocation allowed) -------------
__device__ float g_q[MQ * HID];
__device__ float g_k[MK * HID];
__device__ float g_v[MK * HID];
__device__ float g_y[MQ * HID];
__device__ float g_wqT[C_IN * HID];
__device__ float g_wkT[C_IN * HID];
__device__ float g_wvT[C_IN * HID];
__device__ float g_wreT[HID * C_IN];

// ---------------- weight transpose (coalesced B-tile loads later) -------------
__global__ void prep_weights(const float* __restrict__ wq, const float* __restrict__ wk,
                             const float* __restrict__ wv, const float* __restrict__ wre) {
    int t = blockIdx.x * blockDim.x + threadIdx.x;
    if (t < C_IN * HID) {
        int o = t >> 8;          // wq/wk/wv: [HID][C_IN]
        int c = t & 255;
        g_wqT[c * HID + o] = wq[t];
        g_wkT[c * HID + o] = wk[t];
        g_wvT[c * HID + o] = wv[t];
        int co = t >> 7;         // wre: [C_IN][HID]
        int h  = t & 127;
        g_wreT[h * C_IN + co] = wre[t];
    }
}

// ---------------- Q projection: [25088,256] x [256,128] ----------------------
// tile 64(M) x 128(N), KC=16, 256 threads, 4x8 micro-tile
__global__ void proj_q_kernel(const float* __restrict__ rois, const float* __restrict__ bq) {
    __shared__ float As[16 * 64];
    __shared__ float Bs[16 * 128];
    const int tid = threadIdx.x;
    const int m0  = blockIdx.x * 64;
    const int ty  = tid >> 4, tx = tid & 15;

    float acc[4][8];
#pragma unroll
    for (int i = 0; i < 4; i++)
#pragma unroll
        for (int j = 0; j < 8; j++) acc[i][j] = 0.f;

    for (int kc = 0; kc < C_IN; kc += 16) {
#pragma unroll
        for (int i = 0; i < 4; i++) {       // 1024 A elements
            int e = tid + i * 256;
            int mm = e & 63, k = e >> 6;
            int m = m0 + mm;
            int n = m / HW;
            int p = m - n * HW;
            As[k * 64 + mm] = rois[(n * C_IN + kc + k) * HW + p];
        }
#pragma unroll
        for (int i = 0; i < 8; i++) {       // 2048 B elements
            int e = tid + i * 256;
            int nn = e & 127, k = e >> 7;
            Bs[k * 128 + nn] = g_wqT[(kc + k) * HID + nn];
        }
        __syncthreads();
#pragma unroll
        for (int k = 0; k < 16; k++) {
            float4 a  = *(const float4*)&As[k * 64 + ty * 4];
            float4 b0 = *(const float4*)&Bs[k * 128 + tx * 8];
            float4 b1 = *(const float4*)&Bs[k * 128 + tx * 8 + 4];
            float av[4] = {a.x, a.y, a.z, a.w};
            float bv[8] = {b0.x, b0.y, b0.z, b0.w, b1.x, b1.y, b1.z, b1.w};
#pragma unroll
            for (int i = 0; i < 4; i++)
#pragma unroll
                for (int j = 0; j < 8; j++) acc[i][j] += av[i] * bv[j];
        }
        __syncthreads();
    }
    float b0 = bq[tx * 8 + 0], b1 = bq[tx * 8 + 1], b2 = bq[tx * 8 + 2], b3 = bq[tx * 8 + 3];
    float b4 = bq[tx * 8 + 4], b5 = bq[tx * 8 + 5], b6 = bq[tx * 8 + 6], b7 = bq[tx * 8 + 7];
#pragma unroll
    for (int i = 0; i < 4; i++) {
        int m = m0 + ty * 4 + i;
        float4 o0 = make_float4(acc[i][0] + b0, acc[i][1] + b1, acc[i][2] + b2, acc[i][3] + b3);
        float4 o1 = make_float4(acc[i][4] + b4, acc[i][5] + b5, acc[i][6] + b6, acc[i][7] + b7);
        *(float4*)&g_q[m * HID + tx * 8]     = o0;
        *(float4*)&g_q[m * HID + tx * 8 + 4] = o1;
    }
}

// ---------------- K/V projection with fused 2x2 maxpool -----------------------
__global__ void proj_kv_kernel(const float* __restrict__ rois, const float* __restrict__ bias,
                               int which) {
    __shared__ float As[16 * 64];
    __shared__ float Bs[16 * 128];
    const float* wT  = which ? g_wvT : g_wkT;
    float*       dst = which ? g_v   : g_k;
    const int tid = threadIdx.x;
    const int m0  = blockIdx.x * 64;
    const int ty  = tid >> 4, tx = tid & 15;

    float acc[4][8];
#pragma unroll
    for (int i = 0; i < 4; i++)
#pragma unroll
        for (int j = 0; j < 8; j++) acc[i][j] = 0.f;

    for (int kc = 0; kc < C_IN; kc += 16) {
#pragma unroll
        for (int i = 0; i < 4; i++) {
            int e = tid + i * 256;
            int mm = e & 63, k = e >> 6;
            int m = m0 + mm;
            int n = m / PHW;
            int pp = m - n * PHW;
            int py = pp / 7;
            int px = pp - py * 7;
            const float* src = rois + (n * C_IN + kc + k) * HW + py * 28 + px * 2;
            float a = fmaxf(fmaxf(src[0], src[1]), fmaxf(src[14], src[15]));
            As[k * 64 + mm] = a;
        }
#pragma unroll
        for (int i = 0; i < 8; i++) {
            int e = tid + i * 256;
            int nn = e & 127, k = e >> 7;
            Bs[k * 128 + nn] = wT[(kc + k) * HID + nn];
        }
        __syncthreads();
#pragma unroll
        for (int k = 0; k < 16; k++) {
            float4 a  = *(const float4*)&As[k * 64 + ty * 4];
            float4 b0 = *(const float4*)&Bs[k * 128 + tx * 8];
            float4 b1 = *(const float4*)&Bs[k * 128 + tx * 8 + 4];
            float av[4] = {a.x, a.y, a.z, a.w};
            float bv[8] = {b0.x, b0.y, b0.z, b0.w, b1.x, b1.y, b1.z, b1.w};
#pragma unroll
            for (int i = 0; i < 4; i++)
#pragma unroll
                for (int j = 0; j < 8; j++) acc[i][j] += av[i] * bv[j];
        }
        __syncthreads();
    }
#pragma unroll
    for (int i = 0; i < 4; i++) {
        int m = m0 + ty * 4 + i;
#pragma unroll
        for (int j = 0; j < 8; j++) {
            int o = tx * 8 + j;
            dst[m * HID + o] = acc[i][j] + bias[o];
        }
    }
}

// ---------------- flash attention: BQ=64, BK=64, D=128 ------------------------
// smem: Qt[128][68] (transposed), Kt[128][68] (transposed), V[64][132], Pt[64][68]
extern __shared__ float sm_attn[];
__global__ void attn_kernel() {
    float* smQ = sm_attn;                 // 128*68 = 8704
    float* smK = smQ + 128 * 68;          // 8704
    float* smV = smK + 128 * 68;          // 64*132 = 8448
    float* smP = smV + 64 * 132;          // 64*68  = 4352
    const int tid = threadIdx.x;
    const int ty  = tid >> 4, tx = tid & 15;
    const int b   = blockIdx.y;
    const int q0  = blockIdx.x * 64;

    const float* qbase = g_q + (size_t)(b * NQ_B + q0) * HID;
#pragma unroll
    for (int i = 0; i < 32; i++) {        // 8192 elements, transposed store
        int e = tid + i * 256;
        int h = e & 127, qq = e >> 7;
        smQ[h * 68 + qq] = qbase[qq * HID + h];
    }

    float acc[4][8];
    float mrow[4], lrow[4];
#pragma unroll
    for (int i = 0; i < 4; i++) {
        mrow[i] = -INFINITY;
        lrow[i] = 0.f;
#pragma unroll
        for (int j = 0; j < 8; j++) acc[i][j] = 0.f;
    }

    for (int kc = 0; kc < 49; kc++) {
        const float* kbase = g_k + (size_t)(b * NK_B + kc * 64) * HID;
        const float* vbase = g_v + (size_t)(b * NK_B + kc * 64) * HID;
#pragma unroll
        for (int i = 0; i < 32; i++) {
            int e = tid + i * 256;
            int h = e & 127, kk = e >> 7;
            smK[h * 68 + kk]  = kbase[kk * HID + h];
            smV[kk * 132 + h] = vbase[kk * HID + h];
        }
        __syncthreads();

        // S = Q K^T  (4x4 per thread)
        float s[4][4];
#pragma unroll
        for (int i = 0; i < 4; i++)
#pragma unroll
            for (int j = 0; j < 4; j++) s[i][j] = 0.f;
#pragma unroll 4
        for (int h = 0; h < 128; h++) {
            float4 qv = *(const float4*)&smQ[h * 68 + ty * 4];
            float4 kv = *(const float4*)&smK[h * 68 + tx * 4];
            float qa[4] = {qv.x, qv.y, qv.z, qv.w};
            float ka[4] = {kv.x, kv.y, kv.z, kv.w};
#pragma unroll
            for (int i = 0; i < 4; i++)
#pragma unroll
                for (int j = 0; j < 4; j++) s[i][j] += qa[i] * ka[j];
        }

        // online softmax (rows shared by 16 lanes: same ty → one 16-lane half-warp)
#pragma unroll
        for (int i = 0; i < 4; i++) {
            float mx = fmaxf(fmaxf(s[i][0], s[i][1]), fmaxf(s[i][2], s[i][3]));
#pragma unroll
            for (int off = 1; off < 16; off <<= 1)
                mx = fmaxf(mx, __shfl_xor_sync(0xffffffffu, mx, off));
            float mnew = fmaxf(mrow[i], mx);
            float corr = __expf(mrow[i] - mnew);
            mrow[i] = mnew;
            float rs = 0.f;
#pragma unroll
            for (int j = 0; j < 4; j++) {
                s[i][j] = __expf(s[i][j] - mnew);
                rs += s[i][j];
            }
#pragma unroll
            for (int off = 1; off < 16; off <<= 1)
                rs += __shfl_xor_sync(0xffffffffu, rs, off);
            lrow[i] = lrow[i] * corr + rs;
#pragma unroll
            for (int j = 0; j < 8; j++) acc[i][j] *= corr;
        }

        // write P transposed: Pt[k][q]
#pragma unroll
        for (int i = 0; i < 4; i++)
#pragma unroll
            for (int j = 0; j < 4; j++)
                smP[(tx * 4 + j) * 68 + ty * 4 + i] = s[i][j];
        __syncthreads();

        // Y += P V  (4x8 per thread)
#pragma unroll 4
        for (int kk = 0; kk < 64; kk++) {
            float4 pv = *(const float4*)&smP[kk * 68 + ty * 4];
            float4 v0 = *(const float4*)&smV[kk * 132 + tx * 8];
            float4 v1 = *(const float4*)&smV[kk * 132 + tx * 8 + 4];
            float pa[4] = {pv.x, pv.y, pv.z, pv.w};
            float va[8] = {v0.x, v0.y, v0.z, v0.w, v1.x, v1.y, v1.z, v1.w};
#pragma unroll
            for (int i = 0; i < 4; i++)
#pragma unroll
                for (int j = 0; j < 8; j++) acc[i][j] += pa[i] * va[j];
        }
        __syncthreads();
    }

    float* ybase = g_y + (size_t)(b * NQ_B + q0) * HID;
#pragma unroll
    for (int i = 0; i < 4; i++) {
        float inv = 1.0f / lrow[i];
        float4 o0 = make_float4(acc[i][0] * inv, acc[i][1] * inv, acc[i][2] * inv, acc[i][3] * inv);
        float4 o1 = make_float4(acc[i][4] * inv, acc[i][5] * inv, acc[i][6] * inv, acc[i][7] * inv);
        *(float4*)&ybase[(ty * 4 + i) * HID + tx * 8]     = o0;
        *(float4*)&ybase[(ty * 4 + i) * HID + tx * 8 + 4] = o1;
    }
}

// ---------------- epilogue: out = rois + Y * wre^T + bre ----------------------
// [25088,128] x [128,256], tile 64 x 128, grid (392, 2)
__global__ void epilogue_kernel(const float* __restrict__ rois, const float* __restrict__ bre,
                                float* __restrict__ out) {
    __shared__ float As[16 * 68];
    __shared__ float Bs[16 * 128];
    const int tid = threadIdx.x;
    const int m0  = blockIdx.x * 64;
    const int n0  = blockIdx.y * 128;
    const int ty  = tid >> 4, tx = tid & 15;

    float acc[4][8];
#pragma unroll
    for (int i = 0; i < 4; i++)
#pragma unroll
        for (int j = 0; j < 8; j++) acc[i][j] = 0.f;

    const int mm = tid >> 2;
    const int kq = tid & 3;
    for (int kc = 0; kc < HID; kc += 16) {
        float4 a = *(const float4*)&g_y[(size_t)(m0 + mm) * HID + kc + kq * 4];
        As[(kq * 4 + 0) * 68 + mm] = a.x;
        As[(kq * 4 + 1) * 68 + mm] = a.y;
        As[(kq * 4 + 2) * 68 + mm] = a.z;
        As[(kq * 4 + 3) * 68 + mm] = a.w;
#pragma unroll
        for (int i = 0; i < 8; i++) {
            int e = tid + i * 256;
            int nn = e & 127, k = e >> 7;
            Bs[k * 128 + nn] = g_wreT[(kc + k) * C_IN + n0 + nn];
        }
        __syncthreads();
#pragma unroll
        for (int k = 0; k < 16; k++) {
            float4 av4 = *(const float4*)&As[k * 68 + ty * 4];
            float4 b0  = *(const float4*)&Bs[k * 128 + tx * 8];
            float4 b1  = *(const float4*)&Bs[k * 128 + tx * 8 + 4];
            float av[4] = {av4.x, av4.y, av4.z, av4.w};
            float bv[8] = {b0.x, b0.y, b0.z, b0.w, b1.x, b1.y, b1.z, b1.w};
#pragma unroll
            for (int i = 0; i < 4; i++)
#pragma unroll
                for (int j = 0; j < 8; j++) acc[i][j] += av[i] * bv[j];
        }
        __syncthreads();
    }
#pragma unroll
    for (int i = 0; i < 4; i++) {
        int m = m0 + ty * 4 + i;
        int n = m / HW;
        int p = m - n * HW;
#pragma unroll
        for (int j = 0; j < 8; j++) {
            int co = n0 + tx * 8 + j;
            int idx = (n * C_IN + co) * HW + p;
            out[idx] = rois[idx] + acc[i][j] + bre[co];
        }
    }
}

// ---------------- launch ------------------------------------------------------
extern "C" void kernel_launch(void* const* d_in, const int* in_sizes, int n_in,
                              void* d_out, int out_size) {
    const float* rois = (const float*)d_in[0];
    // d_in[1] = feature: only its batch dim matters (BS=2), never read
    const float* wq  = (const float*)d_in[2];
    const float* bq  = (const float*)d_in[3];
    const float* wk  = (const float*)d_in[4];
    const float* bk  = (const float*)d_in[5];
    const float* wv  = (const float*)d_in[6];
    const float* bv  = (const float*)d_in[7];
    const float* wre = (const float*)d_in[8];
    const float* bre = (const float*)d_in[9];
    float* out = (float*)d_out;

    const int attn_smem = (128 * 68 + 128 * 68 + 64 * 132 + 64 * 68) * 4;  // 120832 B
    cudaFuncSetAttribute(attn_kernel, cudaFuncAttributeMaxDynamicSharedMemorySize, attn_smem);

    prep_weights<<<64, 512>>>(wq, wk, wv, wre);
    proj_q_kernel<<<392, 256>>>(rois, bq);
    proj_kv_kernel<<<98, 256>>>(rois, bk, 0);
    proj_kv_kernel<<<98, 256>>>(rois, bv, 1);
    attn_kernel<<<dim3(196, 2), 256, attn_smem>>>();
    epilogue_kernel<<<dim3(392, 2), 256>>>(rois, bre, out);
}

// round 4
// speedup vs baseline: 2.4515x; 2.4515x over previous
#include <cuda_runtime.h>
#include <math.h>
#include <stdint.h>

#define C_IN 256
#define HID  128
#define HW   196      // 14*14
#define PHW  49       // 7*7
#define MQ   25088    // 128 * 196
#define MK   6272     // 128 * 49
#define NQ_B 12544    // per-batch query count
#define NK_B 3136     // per-batch key count

// ---------------- scratch (device globals; no allocation allowed) -------------
__device__ __align__(256) float g_q[MQ * HID];
__device__ __align__(256) float g_k[MK * HID];
__device__ __align__(256) float g_v[MK * HID];
__device__ __align__(256) float g_y[MQ * HID];
__device__ __align__(256) float g_wqT[C_IN * HID];
__device__ __align__(256) float g_wkT[C_IN * HID];
__device__ __align__(256) float g_wvT[C_IN * HID];
__device__ __align__(256) float g_wreT[HID * C_IN];

// ---------------- mma.sync m16n8k8 tf32 (legacy tensor path, sm_80+ PTX) ------
__device__ __forceinline__ void mma_tf32(float& d0, float& d1, float& d2, float& d3,
                                         uint32_t a0, uint32_t a1, uint32_t a2, uint32_t a3,
                                         uint32_t b0, uint32_t b1) {
    asm volatile(
        "mma.sync.aligned.m16n8k8.row.col.f32.tf32.tf32.f32 "
        "{%0,%1,%2,%3}, {%4,%5,%6,%7}, {%8,%9}, {%0,%1,%2,%3};"
        : "+f"(d0), "+f"(d1), "+f"(d2), "+f"(d3)
        : "r"(a0), "r"(a1), "r"(a2), "r"(a3), "r"(b0), "r"(b1));
}

// ---------------- weight transpose --------------------------------------------
__global__ void prep_weights(const float* __restrict__ wq, const float* __restrict__ wk,
                             const float* __restrict__ wv, const float* __restrict__ wre) {
    int t = blockIdx.x * blockDim.x + threadIdx.x;
    if (t < C_IN * HID) {
        int o = t >> 8;
        int c = t & 255;
        g_wqT[c * HID + o] = wq[t];
        g_wkT[c * HID + o] = wk[t];
        g_wvT[c * HID + o] = wv[t];
        int co = t >> 7;
        int h  = t & 127;
        g_wreT[h * C_IN + co] = wre[t];
    }
}

// ---------------- Q projection: [25088,256] x [256,128] ----------------------
__global__ void proj_q_kernel(const float* __restrict__ rois, const float* __restrict__ bq) {
    __shared__ float As[16 * 64];
    __shared__ float Bs[16 * 128];
    const int tid = threadIdx.x;
    const int m0  = blockIdx.x * 64;
    const int ty  = tid >> 4, tx = tid & 15;

    float acc[4][8];
#pragma unroll
    for (int i = 0; i < 4; i++)
#pragma unroll
        for (int j = 0; j < 8; j++) acc[i][j] = 0.f;

    for (int kc = 0; kc < C_IN; kc += 16) {
#pragma unroll
        for (int i = 0; i < 4; i++) {
            int e = tid + i * 256;
            int mm = e & 63, k = e >> 6;
            int m = m0 + mm;
            int n = m / HW;
            int p = m - n * HW;
            As[k * 64 + mm] = rois[(n * C_IN + kc + k) * HW + p];
        }
#pragma unroll
        for (int i = 0; i < 8; i++) {
            int e = tid + i * 256;
            int nn = e & 127, k = e >> 7;
            Bs[k * 128 + nn] = g_wqT[(kc + k) * HID + nn];
        }
        __syncthreads();
#pragma unroll
        for (int k = 0; k < 16; k++) {
            float4 a  = *(const float4*)&As[k * 64 + ty * 4];
            float4 b0 = *(const float4*)&Bs[k * 128 + tx * 8];
            float4 b1 = *(const float4*)&Bs[k * 128 + tx * 8 + 4];
            float av[4] = {a.x, a.y, a.z, a.w};
            float bv[8] = {b0.x, b0.y, b0.z, b0.w, b1.x, b1.y, b1.z, b1.w};
#pragma unroll
            for (int i = 0; i < 4; i++)
#pragma unroll
                for (int j = 0; j < 8; j++) acc[i][j] += av[i] * bv[j];
        }
        __syncthreads();
    }
#pragma unroll
    for (int i = 0; i < 4; i++) {
        int m = m0 + ty * 4 + i;
#pragma unroll
        for (int j = 0; j < 8; j++) {
            int o = tx * 8 + j;
            g_q[m * HID + o] = acc[i][j] + bq[o];
        }
    }
}

// ---------------- K/V projection with fused 2x2 maxpool (grid.y = which) ------
__global__ void proj_kv_kernel(const float* __restrict__ rois,
                               const float* __restrict__ bk_, const float* __restrict__ bv_) {
    __shared__ float As[16 * 64];
    __shared__ float Bs[16 * 128];
    const int which = blockIdx.y;
    const float* wT   = which ? g_wvT : g_wkT;
    const float* bias = which ? bv_   : bk_;
    float*       dst  = which ? g_v   : g_k;
    const int tid = threadIdx.x;
    const int m0  = blockIdx.x * 64;
    const int ty  = tid >> 4, tx = tid & 15;

    float acc[4][8];
#pragma unroll
    for (int i = 0; i < 4; i++)
#pragma unroll
        for (int j = 0; j < 8; j++) acc[i][j] = 0.f;

    for (int kc = 0; kc < C_IN; kc += 16) {
#pragma unroll
        for (int i = 0; i < 4; i++) {
            int e = tid + i * 256;
            int mm = e & 63, k = e >> 6;
            int m = m0 + mm;
            int n = m / PHW;
            int pp = m - n * PHW;
            int py = pp / 7;
            int px = pp - py * 7;
            const float* src = rois + (n * C_IN + kc + k) * HW + py * 28 + px * 2;
            As[k * 64 + mm] = fmaxf(fmaxf(src[0], src[1]), fmaxf(src[14], src[15]));
        }
#pragma unroll
        for (int i = 0; i < 8; i++) {
            int e = tid + i * 256;
            int nn = e & 127, k = e >> 7;
            Bs[k * 128 + nn] = wT[(kc + k) * HID + nn];
        }
        __syncthreads();
#pragma unroll
        for (int k = 0; k < 16; k++) {
            float4 a  = *(const float4*)&As[k * 64 + ty * 4];
            float4 b0 = *(const float4*)&Bs[k * 128 + tx * 8];
            float4 b1 = *(const float4*)&Bs[k * 128 + tx * 8 + 4];
            float av[4] = {a.x, a.y, a.z, a.w};
            float bv[8] = {b0.x, b0.y, b0.z, b0.w, b1.x, b1.y, b1.z, b1.w};
#pragma unroll
            for (int i = 0; i < 4; i++)
#pragma unroll
                for (int j = 0; j < 8; j++) acc[i][j] += av[i] * bv[j];
        }
        __syncthreads();
    }
#pragma unroll
    for (int i = 0; i < 4; i++) {
        int m = m0 + ty * 4 + i;
#pragma unroll
        for (int j = 0; j < 8; j++) {
            int o = tx * 8 + j;
            dst[m * HID + o] = acc[i][j] + bias[o];
        }
    }
}

// ---------------- tf32 HMMA flash attention -----------------------------------
// BQ=64 q/CTA, 4 warps, each warp 16 q rows; 49 chunks of 64 keys.
// smem: sK[64][132] (also stages Q), sV[64][136], sP[64][68]
#define SK_STRIDE 132
#define SV_STRIDE 136
#define SP_STRIDE 68
#define SM_K 0
#define SM_V (64 * SK_STRIDE)                 // 8448
#define SM_P (SM_V + 64 * SV_STRIDE)          // 17152
#define ATTN_SMEM ((SM_P + 64 * SP_STRIDE) * 4)  // 86016 bytes

__global__ void __launch_bounds__(128, 2) attn_mma_kernel() {
    extern __shared__ float sm[];
    float* sK = sm + SM_K;
    float* sV = sm + SM_V;
    float* sP = sm + SM_P;

    const int tid  = threadIdx.x;
    const int warp = tid >> 5;
    const int lane = tid & 31;
    const int gr   = lane >> 2;     // group id (row within fragment)
    const int tg   = lane & 3;      // thread in group
    const int b    = blockIdx.y;
    const int q0   = blockIdx.x * 64;
    const int qrow = warp * 16;     // warp's q-row base within tile

    // ---- stage Q tile [64 q][128 h] into sK, then hoist fragments to regs ----
    const float* qbase = g_q + (size_t)(b * NQ_B + q0) * HID;
#pragma unroll
    for (int i = 0; i < 16; i++) {
        int e = tid + i * 128;
        int row = e >> 5;
        int c4  = (e & 31) * 4;
        float4 v = *(const float4*)(qbase + (size_t)row * HID + c4);
        *(float4*)&sK[row * SK_STRIDE + c4] = v;
    }
    __syncthreads();

    uint32_t qf[16][4];
#pragma unroll
    for (int ks = 0; ks < 16; ks++) {
        qf[ks][0] = __float_as_uint(sK[(qrow + gr) * SK_STRIDE + ks * 8 + tg]);
        qf[ks][1] = __float_as_uint(sK[(qrow + gr + 8) * SK_STRIDE + ks * 8 + tg]);
        qf[ks][2] = __float_as_uint(sK[(qrow + gr) * SK_STRIDE + ks * 8 + tg + 4]);
        qf[ks][3] = __float_as_uint(sK[(qrow + gr + 8) * SK_STRIDE + ks * 8 + tg + 4]);
    }

    float y[16][4];
#pragma unroll
    for (int nt = 0; nt < 16; nt++)
#pragma unroll
        for (int j = 0; j < 4; j++) y[nt][j] = 0.f;
    float lsum0 = 0.f, lsum1 = 0.f;

    const float* kb0 = g_k + (size_t)(b * NK_B) * HID;
    const float* vb0 = g_v + (size_t)(b * NK_B) * HID;

    for (int kc = 0; kc < 49; kc++) {
        __syncthreads();   // previous chunk's PV reads done (also covers q-frag reads)
        const float* kb = kb0 + (size_t)(kc * 64) * HID;
        const float* vb = vb0 + (size_t)(kc * 64) * HID;
#pragma unroll
        for (int i = 0; i < 16; i++) {
            int e = tid + i * 128;
            int row = e >> 5;
            int c4  = (e & 31) * 4;
            *(float4*)&sK[row * SK_STRIDE + c4] = *(const float4*)(kb + (size_t)row * HID + c4);
            *(float4*)&sV[row * SV_STRIDE + c4] = *(const float4*)(vb + (size_t)row * HID + c4);
        }
        __syncthreads();

        // ---- S = Q K^T : m16(q) x n64(keys) per warp ----
        float s[8][4];
#pragma unroll
        for (int nt = 0; nt < 8; nt++)
#pragma unroll
            for (int j = 0; j < 4; j++) s[nt][j] = 0.f;

#pragma unroll
        for (int ks = 0; ks < 16; ks++) {
#pragma unroll
            for (int nt = 0; nt < 8; nt++) {
                uint32_t b0 = __float_as_uint(sK[(nt * 8 + gr) * SK_STRIDE + ks * 8 + tg]);
                uint32_t b1 = __float_as_uint(sK[(nt * 8 + gr) * SK_STRIDE + ks * 8 + tg + 4]);
                mma_tf32(s[nt][0], s[nt][1], s[nt][2], s[nt][3],
                         qf[ks][0], qf[ks][1], qf[ks][2], qf[ks][3], b0, b1);
            }
        }

        // ---- P = exp(S), rowsums, store P to smem (own 16 rows only) ----
#pragma unroll
        for (int nt = 0; nt < 8; nt++) {
            float p0 = __expf(s[nt][0]);
            float p1 = __expf(s[nt][1]);
            float p2 = __expf(s[nt][2]);
            float p3 = __expf(s[nt][3]);
            lsum0 += p0 + p1;
            lsum1 += p2 + p3;
            *(float2*)&sP[(qrow + gr) * SP_STRIDE + nt * 8 + 2 * tg]     = make_float2(p0, p1);
            *(float2*)&sP[(qrow + gr + 8) * SP_STRIDE + nt * 8 + 2 * tg] = make_float2(p2, p3);
        }
        __syncwarp();

        // ---- Y += P V : m16(q) x n128(h), k64(keys) ----
#pragma unroll
        for (int ks = 0; ks < 8; ks++) {
            uint32_t a0 = __float_as_uint(sP[(qrow + gr) * SP_STRIDE + ks * 8 + tg]);
            uint32_t a1 = __float_as_uint(sP[(qrow + gr + 8) * SP_STRIDE + ks * 8 + tg]);
            uint32_t a2 = __float_as_uint(sP[(qrow + gr) * SP_STRIDE + ks * 8 + tg + 4]);
            uint32_t a3 = __float_as_uint(sP[(qrow + gr + 8) * SP_STRIDE + ks * 8 + tg + 4]);
#pragma unroll
            for (int nt = 0; nt < 16; nt++) {
                uint32_t b0 = __float_as_uint(sV[(ks * 8 + tg) * SV_STRIDE + nt * 8 + gr]);
                uint32_t b1 = __float_as_uint(sV[(ks * 8 + tg + 4) * SV_STRIDE + nt * 8 + gr]);
                mma_tf32(y[nt][0], y[nt][1], y[nt][2], y[nt][3], a0, a1, a2, a3, b0, b1);
            }
        }
    }

    // reduce rowsums across the 4 lanes sharing a row (same gr, tg=0..3)
#pragma unroll
    for (int off = 1; off < 4; off <<= 1) {
        lsum0 += __shfl_xor_sync(0xffffffffu, lsum0, off);
        lsum1 += __shfl_xor_sync(0xffffffffu, lsum1, off);
    }
    const float inv0 = 1.0f / lsum0;
    const float inv1 = 1.0f / lsum1;

    float* y0 = g_y + (size_t)(b * NQ_B + q0 + qrow + gr) * HID;
    float* y1 = g_y + (size_t)(b * NQ_B + q0 + qrow + gr + 8) * HID;
#pragma unroll
    for (int nt = 0; nt < 16; nt++) {
        *(float2*)(y0 + nt * 8 + 2 * tg) = make_float2(y[nt][0] * inv0, y[nt][1] * inv0);
        *(float2*)(y1 + nt * 8 + 2 * tg) = make_float2(y[nt][2] * inv1, y[nt][3] * inv1);
    }
}

// ---------------- epilogue: out = rois + Y * wre^T + bre ----------------------
__global__ void epilogue_kernel(const float* __restrict__ rois, const float* __restrict__ bre,
                                float* __restrict__ out) {
    __shared__ float As[16 * 68];
    __shared__ float Bs[16 * 128];
    const int tid = threadIdx.x;
    const int m0  = blockIdx.x * 64;
    const int n0  = blockIdx.y * 128;
    const int ty  = tid >> 4, tx = tid & 15;

    float acc[4][8];
#pragma unroll
    for (int i = 0; i < 4; i++)
#pragma unroll
        for (int j = 0; j < 8; j++) acc[i][j] = 0.f;

    const int mm = tid >> 2;
    const int kq = tid & 3;
    for (int kc = 0; kc < HID; kc += 16) {
        float4 a = *(const float4*)&g_y[(size_t)(m0 + mm) * HID + kc + kq * 4];
        As[(kq * 4 + 0) * 68 + mm] = a.x;
        As[(kq * 4 + 1) * 68 + mm] = a.y;
        As[(kq * 4 + 2) * 68 + mm] = a.z;
        As[(kq * 4 + 3) * 68 + mm] = a.w;
#pragma unroll
        for (int i = 0; i < 8; i++) {
            int e = tid + i * 256;
            int nn = e & 127, k = e >> 7;
            Bs[k * 128 + nn] = g_wreT[(kc + k) * C_IN + n0 + nn];
        }
        __syncthreads();
#pragma unroll
        for (int k = 0; k < 16; k++) {
            float4 av4 = *(const float4*)&As[k * 68 + ty * 4];
            float4 b0  = *(const float4*)&Bs[k * 128 + tx * 8];
            float4 b1  = *(const float4*)&Bs[k * 128 + tx * 8 + 4];
            float av[4] = {av4.x, av4.y, av4.z, av4.w};
            float bv[8] = {b0.x, b0.y, b0.z, b0.w, b1.x, b1.y, b1.z, b1.w};
#pragma unroll
            for (int i = 0; i < 4; i++)
#pragma unroll
                for (int j = 0; j < 8; j++) acc[i][j] += av[i] * bv[j];
        }
        __syncthreads();
    }
#pragma unroll
    for (int i = 0; i < 4; i++) {
        int m = m0 + ty * 4 + i;
        int n = m / HW;
        int p = m - n * HW;
#pragma unroll
        for (int j = 0; j < 8; j++) {
            int co = n0 + tx * 8 + j;
            int idx = (n * C_IN + co) * HW + p;
            out[idx] = rois[idx] + acc[i][j] + bre[co];
        }
    }
}

// ---------------- launch ------------------------------------------------------
extern "C" void kernel_launch(void* const* d_in, const int* in_sizes, int n_in,
                              void* d_out, int out_size) {
    const float* rois = (const float*)d_in[0];
    const float* wq  = (const float*)d_in[2];
    const float* bq  = (const float*)d_in[3];
    const float* wk  = (const float*)d_in[4];
    const float* bk  = (const float*)d_in[5];
    const float* wv  = (const float*)d_in[6];
    const float* bv  = (const float*)d_in[7];
    const float* wre = (const float*)d_in[8];
    const float* bre = (const float*)d_in[9];
    float* out = (float*)d_out;

    cudaFuncSetAttribute(attn_mma_kernel, cudaFuncAttributeMaxDynamicSharedMemorySize, ATTN_SMEM);

    prep_weights<<<64, 512>>>(wq, wk, wv, wre);
    proj_q_kernel<<<392, 256>>>(rois, bq);
    proj_kv_kernel<<<dim3(98, 2), 256>>>(rois, bk, bv);
    attn_mma_kernel<<<dim3(196, 2), 128, ATTN_SMEM>>>();
    epilogue_kernel<<<dim3(392, 2), 256>>>(rois, bre, out);
}

// round 5
// speedup vs baseline: 3.6008x; 1.4688x over previous
#include <cuda_runtime.h>
#include <math.h>
#include <stdint.h>

#define C_IN 256
#define HID  128
#define HW   196      // 14*14
#define PHW  49       // 7*7
#define MQ   25088    // 128 * 196
#define MK   6272     // 128 * 49
#define NQ_B 12544    // per-batch query count
#define NK_B 3136     // per-batch key count

// ---------------- scratch (device globals; no allocation allowed) -------------
__device__ __align__(256) float g_q[MQ * HID];
__device__ __align__(256) float g_k[MK * HID];
__device__ __align__(256) float g_vT[2 * HID * NK_B];   // [b][h][key]
__device__ __align__(256) float g_y[MQ * HID];
__device__ __align__(256) float g_wqT[C_IN * HID];
__device__ __align__(256) float g_wkT[C_IN * HID];
__device__ __align__(256) float g_wvT[C_IN * HID];
__device__ __align__(256) float g_wreT[HID * C_IN];

// ---------------- mma.sync m16n8k8 tf32 ---------------------------------------
__device__ __forceinline__ void mma_tf32(float& d0, float& d1, float& d2, float& d3,
                                         uint32_t a0, uint32_t a1, uint32_t a2, uint32_t a3,
                                         uint32_t b0, uint32_t b1) {
    asm volatile(
        "mma.sync.aligned.m16n8k8.row.col.f32.tf32.tf32.f32 "
        "{%0,%1,%2,%3}, {%4,%5,%6,%7}, {%8,%9}, {%0,%1,%2,%3};"
        : "+f"(d0), "+f"(d1), "+f"(d2), "+f"(d3)
        : "r"(a0), "r"(a1), "r"(a2), "r"(a3), "r"(b0), "r"(b1));
}

__device__ __forceinline__ uint32_t smem_u32(const void* p) {
    uint32_t a;
    asm("{ .reg .u64 t; cvta.to.shared.u64 t, %1; cvt.u32.u64 %0, t; }" : "=r"(a) : "l"(p));
    return a;
}
__device__ __forceinline__ void cpasync16(uint32_t dst, const void* src) {
    asm volatile("cp.async.cg.shared.global [%0], [%1], 16;" :: "r"(dst), "l"(src));
}
#define CP_COMMIT() asm volatile("cp.async.commit_group;" ::: "memory")
#define CP_WAIT(N)  asm volatile("cp.async.wait_group %0;" :: "n"(N) : "memory")

// ---------------- weight transpose --------------------------------------------
__global__ void prep_weights(const float* __restrict__ wq, const float* __restrict__ wk,
                             const float* __restrict__ wv, const float* __restrict__ wre) {
    int t = blockIdx.x * blockDim.x + threadIdx.x;
    if (t < C_IN * HID) {
        int o = t >> 8;
        int c = t & 255;
        g_wqT[c * HID + o] = wq[t];
        g_wkT[c * HID + o] = wk[t];
        g_wvT[c * HID + o] = wv[t];
        int co = t >> 7;
        int h  = t & 127;
        g_wreT[h * C_IN + co] = wre[t];
    }
}

// ---------------- Q projection: [25088,256] x [256,128] ----------------------
__global__ void proj_q_kernel(const float* __restrict__ rois, const float* __restrict__ bq) {
    __shared__ float As[16 * 64];
    __shared__ float Bs[16 * 128];
    const int tid = threadIdx.x;
    const int m0  = blockIdx.x * 64;
    const int ty  = tid >> 4, tx = tid & 15;

    float acc[4][8];
#pragma unroll
    for (int i = 0; i < 4; i++)
#pragma unroll
        for (int j = 0; j < 8; j++) acc[i][j] = 0.f;

    for (int kc = 0; kc < C_IN; kc += 16) {
#pragma unroll
        for (int i = 0; i < 4; i++) {
            int e = tid + i * 256;
            int mm = e & 63, k = e >> 6;
            int m = m0 + mm;
            int n = m / HW;
            int p = m - n * HW;
            As[k * 64 + mm] = rois[(n * C_IN + kc + k) * HW + p];
        }
#pragma unroll
        for (int i = 0; i < 8; i++) {
            int e = tid + i * 256;
            int nn = e & 127, k = e >> 7;
            Bs[k * 128 + nn] = g_wqT[(kc + k) * HID + nn];
        }
        __syncthreads();
#pragma unroll
        for (int k = 0; k < 16; k++) {
            float4 a  = *(const float4*)&As[k * 64 + ty * 4];
            float4 b0 = *(const float4*)&Bs[k * 128 + tx * 8];
            float4 b1 = *(const float4*)&Bs[k * 128 + tx * 8 + 4];
            float av[4] = {a.x, a.y, a.z, a.w};
            float bv[8] = {b0.x, b0.y, b0.z, b0.w, b1.x, b1.y, b1.z, b1.w};
#pragma unroll
            for (int i = 0; i < 4; i++)
#pragma unroll
                for (int j = 0; j < 8; j++) acc[i][j] += av[i] * bv[j];
        }
        __syncthreads();
    }
#pragma unroll
    for (int i = 0; i < 4; i++) {
        int m = m0 + ty * 4 + i;
#pragma unroll
        for (int j = 0; j < 8; j++) {
            int o = tx * 8 + j;
            g_q[m * HID + o] = acc[i][j] + bq[o];
        }
    }
}

// ---------------- K/V projection with fused 2x2 maxpool (grid.y = which) ------
__global__ void proj_kv_kernel(const float* __restrict__ rois,
                               const float* __restrict__ bk_, const float* __restrict__ bv_) {
    __shared__ float As[16 * 64];
    __shared__ float Bs[16 * 128];
    const int which = blockIdx.y;
    const float* wT   = which ? g_wvT : g_wkT;
    const float* bias = which ? bv_   : bk_;
    const int tid = threadIdx.x;
    const int m0  = blockIdx.x * 64;
    const int ty  = tid >> 4, tx = tid & 15;

    float acc[4][8];
#pragma unroll
    for (int i = 0; i < 4; i++)
#pragma unroll
        for (int j = 0; j < 8; j++) acc[i][j] = 0.f;

    for (int kc = 0; kc < C_IN; kc += 16) {
#pragma unroll
        for (int i = 0; i < 4; i++) {
            int e = tid + i * 256;
            int mm = e & 63, k = e >> 6;
            int m = m0 + mm;
            int n = m / PHW;
            int pp = m - n * PHW;
            int py = pp / 7;
            int px = pp - py * 7;
            const float* src = rois + (n * C_IN + kc + k) * HW + py * 28 + px * 2;
            As[k * 64 + mm] = fmaxf(fmaxf(src[0], src[1]), fmaxf(src[14], src[15]));
        }
#pragma unroll
        for (int i = 0; i < 8; i++) {
            int e = tid + i * 256;
            int nn = e & 127, k = e >> 7;
            Bs[k * 128 + nn] = wT[(kc + k) * HID + nn];
        }
        __syncthreads();
#pragma unroll
        for (int k = 0; k < 16; k++) {
            float4 a  = *(const float4*)&As[k * 64 + ty * 4];
            float4 b0 = *(const float4*)&Bs[k * 128 + tx * 8];
            float4 b1 = *(const float4*)&Bs[k * 128 + tx * 8 + 4];
            float av[4] = {a.x, a.y, a.z, a.w};
            float bv[8] = {b0.x, b0.y, b0.z, b0.w, b1.x, b1.y, b1.z, b1.w};
#pragma unroll
            for (int i = 0; i < 4; i++)
#pragma unroll
                for (int j = 0; j < 8; j++) acc[i][j] += av[i] * bv[j];
        }
        __syncthreads();
    }
#pragma unroll
    for (int i = 0; i < 4; i++) {
        int m = m0 + ty * 4 + i;
        if (which == 0) {
#pragma unroll
            for (int j = 0; j < 8; j++) {
                int o = tx * 8 + j;
                g_k[m * HID + o] = acc[i][j] + bias[o];
            }
        } else {
            int n = m / PHW;
            int pp = m - n * PHW;
            int bb = n >> 6;
            int key = (n & 63) * PHW + pp;
#pragma unroll
            for (int j = 0; j < 8; j++) {
                int o = tx * 8 + j;
                g_vT[((size_t)(bb * HID + o)) * NK_B + key] = acc[i][j] + bias[o];
            }
        }
    }
}

// ---------------- tf32 HMMA flash attention (cp.async pipelined) ---------------
// BQ=64/CTA, 4 warps x 16 q-rows; 49 chunks of 64 keys.
// smem: K double-buffered [2][64][132], Vt [128][68]. P lives in registers.
#define SK_STRIDE 132
#define SK_BUF    (64 * SK_STRIDE)     // 8448 floats
#define SV_STRIDE 68
#define SM_V      (2 * SK_BUF)         // 16896
#define ATTN_FLOATS (SM_V + 128 * SV_STRIDE)   // 16896 + 8704 = 25600
#define ATTN_SMEM (ATTN_FLOATS * 4)            // 102400 bytes

__global__ void __launch_bounds__(128, 2) attn_mma_kernel() {
    extern __shared__ float sm[];
    float* sK  = sm;
    float* sVt = sm + SM_V;
    const uint32_t sKa  = smem_u32(sK);
    const uint32_t sVta = smem_u32(sVt);

    const int tid  = threadIdx.x;
    const int warp = tid >> 5;
    const int lane = tid & 31;
    const int gr   = lane >> 2;
    const int tg   = lane & 3;
    const int b    = blockIdx.y;
    const int q0   = blockIdx.x * 64;
    const int qrow = warp * 16;
    const int src1 = (lane & 28) | (tg >> 1);   // shuffle source for P cols tg
    const int src2 = src1 + 2;                  // for cols tg+4

    // ---- stage Q [64 q][128 h] into sVt area (stride 132), hoist fragments ----
    const float* qbase = g_q + (size_t)(b * NQ_B + q0) * HID;
#pragma unroll
    for (int i = 0; i < 16; i++) {
        int e = tid + i * 128;
        int row = e >> 5;
        int c4  = (e & 31) * 4;
        *(float4*)&sVt[row * SK_STRIDE + c4] = *(const float4*)(qbase + (size_t)row * HID + c4);
    }
    __syncthreads();

    uint32_t qf[16][4];
#pragma unroll
    for (int ks = 0; ks < 16; ks++) {
        qf[ks][0] = __float_as_uint(sVt[(qrow + gr) * SK_STRIDE + ks * 8 + tg]);
        qf[ks][1] = __float_as_uint(sVt[(qrow + gr + 8) * SK_STRIDE + ks * 8 + tg]);
        qf[ks][2] = __float_as_uint(sVt[(qrow + gr) * SK_STRIDE + ks * 8 + tg + 4]);
        qf[ks][3] = __float_as_uint(sVt[(qrow + gr + 8) * SK_STRIDE + ks * 8 + tg + 4]);
    }
    __syncthreads();   // Q reads done; sVt now free for V

    const float* kb0 = g_k + (size_t)(b * NK_B) * HID;
    const float* vb0 = g_vT + (size_t)(b * HID) * NK_B;

    // prefetch K[0] into buf0, V[0]
#pragma unroll
    for (int i = 0; i < 16; i++) {
        int e = tid + i * 128;
        int row = e >> 5;
        int c4  = e & 31;
        cpasync16(sKa + (row * SK_STRIDE + c4 * 4) * 4, kb0 + (size_t)row * HID + c4 * 4);
    }
    CP_COMMIT();
#pragma unroll
    for (int i = 0; i < 16; i++) {
        int e = tid + i * 128;
        int row = e >> 4;
        int c4  = e & 15;
        cpasync16(sVta + (row * SV_STRIDE + c4 * 4) * 4, vb0 + (size_t)row * NK_B + c4 * 4);
    }
    CP_COMMIT();

    float y[16][4];
#pragma unroll
    for (int nt = 0; nt < 16; nt++)
#pragma unroll
        for (int j = 0; j < 4; j++) y[nt][j] = 0.f;
    float lsum0 = 0.f, lsum1 = 0.f;

    for (int kc = 0; kc < 49; kc++) {
        // wait K[kc] (oldest pending group), all warps
        CP_WAIT(1);
        __syncthreads();
        const float* sKb = sK + (kc & 1) * SK_BUF;

        // prefetch K[kc+1] into other buffer (free since kc-1's S finished)
        if (kc < 48) {
            const float* kb = kb0 + (size_t)((kc + 1) * 64) * HID;
            uint32_t dstb = sKa + (((kc + 1) & 1) * SK_BUF) * 4;
#pragma unroll
            for (int i = 0; i < 16; i++) {
                int e = tid + i * 128;
                int row = e >> 5;
                int c4  = e & 31;
                cpasync16(dstb + (row * SK_STRIDE + c4 * 4) * 4, kb + (size_t)row * HID + c4 * 4);
            }
            CP_COMMIT();
        }

        // ---- S = Q K^T : m16 x n64 per warp ----
        float s[8][4];
#pragma unroll
        for (int nt = 0; nt < 8; nt++)
#pragma unroll
            for (int j = 0; j < 4; j++) s[nt][j] = 0.f;
#pragma unroll
        for (int ks = 0; ks < 16; ks++) {
#pragma unroll
            for (int nt = 0; nt < 8; nt++) {
                uint32_t b0 = __float_as_uint(sKb[(nt * 8 + gr) * SK_STRIDE + ks * 8 + tg]);
                uint32_t b1 = __float_as_uint(sKb[(nt * 8 + gr) * SK_STRIDE + ks * 8 + tg + 4]);
                mma_tf32(s[nt][0], s[nt][1], s[nt][2], s[nt][3],
                         qf[ks][0], qf[ks][1], qf[ks][2], qf[ks][3], b0, b1);
            }
        }

        // ---- P = exp(S) in registers; rowsums ----
#pragma unroll
        for (int nt = 0; nt < 8; nt++) {
            s[nt][0] = __expf(s[nt][0]);
            s[nt][1] = __expf(s[nt][1]);
            s[nt][2] = __expf(s[nt][2]);
            s[nt][3] = __expf(s[nt][3]);
            lsum0 += s[nt][0] + s[nt][1];
            lsum1 += s[nt][2] + s[nt][3];
        }

        // wait V[kc]; (pending: V[kc], K[kc+1]) except last chunk (V[kc] only)
        if (kc < 48) { CP_WAIT(1); } else { CP_WAIT(0); }
        __syncthreads();

        // ---- Y += P V : A-fragments of P built via shuffles from s ----
#pragma unroll
        for (int ks = 0; ks < 8; ks++) {
            float u0 = __shfl_sync(0xffffffffu, s[ks][0], src1, 32);
            float u1 = __shfl_sync(0xffffffffu, s[ks][1], src1, 32);
            float u2 = __shfl_sync(0xffffffffu, s[ks][2], src1, 32);
            float u3 = __shfl_sync(0xffffffffu, s[ks][3], src1, 32);
            float w0 = __shfl_sync(0xffffffffu, s[ks][0], src2, 32);
            float w1 = __shfl_sync(0xffffffffu, s[ks][1], src2, 32);
            float w2 = __shfl_sync(0xffffffffu, s[ks][2], src2, 32);
            float w3 = __shfl_sync(0xffffffffu, s[ks][3], src2, 32);
            uint32_t a0 = __float_as_uint((tg & 1) ? u1 : u0);
            uint32_t a1 = __float_as_uint((tg & 1) ? u3 : u2);
            uint32_t a2 = __float_as_uint((tg & 1) ? w1 : w0);
            uint32_t a3 = __float_as_uint((tg & 1) ? w3 : w2);
#pragma unroll
            for (int nt = 0; nt < 16; nt++) {
                uint32_t b0 = __float_as_uint(sVt[(nt * 8 + gr) * SV_STRIDE + ks * 8 + tg]);
                uint32_t b1 = __float_as_uint(sVt[(nt * 8 + gr) * SV_STRIDE + ks * 8 + tg + 4]);
                mma_tf32(y[nt][0], y[nt][1], y[nt][2], y[nt][3], a0, a1, a2, a3, b0, b1);
            }
        }

        // V buffer free after all warps done; prefetch V[kc+1]
        __syncthreads();
        if (kc < 48) {
            const float* vb = vb0 + (kc + 1) * 64;
#pragma unroll
            for (int i = 0; i < 16; i++) {
                int e = tid + i * 128;
                int row = e >> 4;
                int c4  = e & 15;
                cpasync16(sVta + (row * SV_STRIDE + c4 * 4) * 4, vb + (size_t)row * NK_B + c4 * 4);
            }
            CP_COMMIT();
        }
    }

    // reduce rowsums across 4 lanes sharing a row
#pragma unroll
    for (int off = 1; off < 4; off <<= 1) {
        lsum0 += __shfl_xor_sync(0xffffffffu, lsum0, off);
        lsum1 += __shfl_xor_sync(0xffffffffu, lsum1, off);
    }
    const float inv0 = 1.0f / lsum0;
    const float inv1 = 1.0f / lsum1;

    float* y0 = g_y + (size_t)(b * NQ_B + q0 + qrow + gr) * HID;
    float* y1 = g_y + (size_t)(b * NQ_B + q0 + qrow + gr + 8) * HID;
#pragma unroll
    for (int nt = 0; nt < 16; nt++) {
        *(float2*)(y0 + nt * 8 + 2 * tg) = make_float2(y[nt][0] * inv0, y[nt][1] * inv0);
        *(float2*)(y1 + nt * 8 + 2 * tg) = make_float2(y[nt][2] * inv1, y[nt][3] * inv1);
    }
}

// ---------------- epilogue: out = rois + Y * wre^T + bre ----------------------
__global__ void epilogue_kernel(const float* __restrict__ rois, const float* __restrict__ bre,
                                float* __restrict__ out) {
    __shared__ float As[16 * 68];
    __shared__ float Bs[16 * 128];
    const int tid = threadIdx.x;
    const int m0  = blockIdx.x * 64;
    const int n0  = blockIdx.y * 128;
    const int ty  = tid >> 4, tx = tid & 15;

    float acc[4][8];
#pragma unroll
    for (int i = 0; i < 4; i++)
#pragma unroll
        for (int j = 0; j < 8; j++) acc[i][j] = 0.f;

    const int mm = tid >> 2;
    const int kq = tid & 3;
    for (int kc = 0; kc < HID; kc += 16) {
        float4 a = *(const float4*)&g_y[(size_t)(m0 + mm) * HID + kc + kq * 4];
        As[(kq * 4 + 0) * 68 + mm] = a.x;
        As[(kq * 4 + 1) * 68 + mm] = a.y;
        As[(kq * 4 + 2) * 68 + mm] = a.z;
        As[(kq * 4 + 3) * 68 + mm] = a.w;
#pragma unroll
        for (int i = 0; i < 8; i++) {
            int e = tid + i * 256;
            int nn = e & 127, k = e >> 7;
            Bs[k * 128 + nn] = g_wreT[(kc + k) * C_IN + n0 + nn];
        }
        __syncthreads();
#pragma unroll
        for (int k = 0; k < 16; k++) {
            float4 av4 = *(const float4*)&As[k * 68 + ty * 4];
            float4 b0  = *(const float4*)&Bs[k * 128 + tx * 8];
            float4 b1  = *(const float4*)&Bs[k * 128 + tx * 8 + 4];
            float av[4] = {av4.x, av4.y, av4.z, av4.w};
            float bv[8] = {b0.x, b0.y, b0.z, b0.w, b1.x, b1.y, b1.z, b1.w};
#pragma unroll
            for (int i = 0; i < 4; i++)
#pragma unroll
                for (int j = 0; j < 8; j++) acc[i][j] += av[i] * bv[j];
        }
        __syncthreads();
    }
#pragma unroll
    for (int i = 0; i < 4; i++) {
        int m = m0 + ty * 4 + i;
        int n = m / HW;
        int p = m - n * HW;
#pragma unroll
        for (int j = 0; j < 8; j++) {
            int co = n0 + tx * 8 + j;
            int idx = (n * C_IN + co) * HW + p;
            out[idx] = rois[idx] + acc[i][j] + bre[co];
        }
    }
}

// ---------------- launch ------------------------------------------------------
extern "C" void kernel_launch(void* const* d_in, const int* in_sizes, int n_in,
                              void* d_out, int out_size) {
    const float* rois = (const float*)d_in[0];
    const float* wq  = (const float*)d_in[2];
    const float* bq  = (const float*)d_in[3];
    const float* wk  = (const float*)d_in[4];
    const float* bk  = (const float*)d_in[5];
    const float* wv  = (const float*)d_in[6];
    const float* bv  = (const float*)d_in[7];
    const float* wre = (const float*)d_in[8];
    const float* bre = (const float*)d_in[9];
    float* out = (float*)d_out;

    cudaFuncSetAttribute(attn_mma_kernel, cudaFuncAttributeMaxDynamicSharedMemorySize, ATTN_SMEM);

    prep_weights<<<64, 512>>>(wq, wk, wv, wre);
    proj_q_kernel<<<392, 256>>>(rois, bq);
    proj_kv_kernel<<<dim3(98, 2), 256>>>(rois, bk, bv);
    attn_mma_kernel<<<dim3(196, 2), 128, ATTN_SMEM>>>();
    epilogue_kernel<<<dim3(392, 2), 256>>>(rois, bre, out);
}

// round 6
// speedup vs baseline: 4.2203x; 1.1721x over previous
#include <cuda_runtime.h>
#include <cuda_fp16.h>
#include <math.h>
#include <stdint.h>

#define C_IN 256
#define HID  128
#define HW   196      // 14*14
#define PHW  49       // 7*7
#define MQ   25088    // 128 * 196
#define MK   6272     // 128 * 49
#define NQ_B 12544    // per-batch query count
#define NK_B 3136     // per-batch key count

// ---------------- scratch (device globals; no allocation allowed) -------------
__device__ __align__(256) __half g_qh[MQ * HID];
__device__ __align__(256) __half g_kh[MK * HID];
__device__ __align__(256) __half g_vTh[2 * HID * NK_B];  // [b][h][key]
__device__ __align__(256) float  g_y[MQ * HID];
__device__ __align__(256) float  g_wqT[C_IN * HID];
__device__ __align__(256) float  g_wkT[C_IN * HID];
__device__ __align__(256) float  g_wvT[C_IN * HID];
__device__ __align__(256) float  g_wreT[HID * C_IN];

// ---------------- mma.sync m16n8k16 f16 (f32 accum) ---------------------------
__device__ __forceinline__ void mma_f16(float& d0, float& d1, float& d2, float& d3,
                                        uint32_t a0, uint32_t a1, uint32_t a2, uint32_t a3,
                                        uint32_t b0, uint32_t b1) {
    asm volatile(
        "mma.sync.aligned.m16n8k16.row.col.f32.f16.f16.f32 "
        "{%0,%1,%2,%3}, {%4,%5,%6,%7}, {%8,%9}, {%0,%1,%2,%3};"
        : "+f"(d0), "+f"(d1), "+f"(d2), "+f"(d3)
        : "r"(a0), "r"(a1), "r"(a2), "r"(a3), "r"(b0), "r"(b1));
}

__device__ __forceinline__ uint32_t smem_u32(const void* p) {
    uint32_t a;
    asm("{ .reg .u64 t; cvta.to.shared.u64 t, %1; cvt.u32.u64 %0, t; }" : "=r"(a) : "l"(p));
    return a;
}
__device__ __forceinline__ void cpasync16(uint32_t dst, const void* src) {
    asm volatile("cp.async.cg.shared.global [%0], [%1], 16;" :: "r"(dst), "l"(src));
}
#define CP_COMMIT() asm volatile("cp.async.commit_group;" ::: "memory")
#define CP_WAIT(N)  asm volatile("cp.async.wait_group %0;" :: "n"(N) : "memory")

// ---------------- weight transpose --------------------------------------------
__global__ void prep_weights(const float* __restrict__ wq, const float* __restrict__ wk,
                             const float* __restrict__ wv, const float* __restrict__ wre) {
    int t = blockIdx.x * blockDim.x + threadIdx.x;
    if (t < C_IN * HID) {
        int o = t >> 8;
        int c = t & 255;
        g_wqT[c * HID + o] = wq[t];
        g_wkT[c * HID + o] = wk[t];
        g_wvT[c * HID + o] = wv[t];
        int co = t >> 7;
        int h  = t & 127;
        g_wreT[h * C_IN + co] = wre[t];
    }
}

// ---------------- Q projection: [25088,256] x [256,128] -> fp16 ---------------
__global__ void proj_q_kernel(const float* __restrict__ rois, const float* __restrict__ bq) {
    __shared__ float As[16 * 64];
    __shared__ float Bs[16 * 128];
    const int tid = threadIdx.x;
    const int m0  = blockIdx.x * 64;
    const int ty  = tid >> 4, tx = tid & 15;

    float acc[4][8];
#pragma unroll
    for (int i = 0; i < 4; i++)
#pragma unroll
        for (int j = 0; j < 8; j++) acc[i][j] = 0.f;

    for (int kc = 0; kc < C_IN; kc += 16) {
#pragma unroll
        for (int i = 0; i < 4; i++) {
            int e = tid + i * 256;
            int mm = e & 63, k = e >> 6;
            int m = m0 + mm;
            int n = m / HW;
            int p = m - n * HW;
            As[k * 64 + mm] = rois[(n * C_IN + kc + k) * HW + p];
        }
#pragma unroll
        for (int i = 0; i < 8; i++) {
            int e = tid + i * 256;
            int nn = e & 127, k = e >> 7;
            Bs[k * 128 + nn] = g_wqT[(kc + k) * HID + nn];
        }
        __syncthreads();
#pragma unroll
        for (int k = 0; k < 16; k++) {
            float4 a  = *(const float4*)&As[k * 64 + ty * 4];
            float4 b0 = *(const float4*)&Bs[k * 128 + tx * 8];
            float4 b1 = *(const float4*)&Bs[k * 128 + tx * 8 + 4];
            float av[4] = {a.x, a.y, a.z, a.w};
            float bv[8] = {b0.x, b0.y, b0.z, b0.w, b1.x, b1.y, b1.z, b1.w};
#pragma unroll
            for (int i = 0; i < 4; i++)
#pragma unroll
                for (int j = 0; j < 8; j++) acc[i][j] += av[i] * bv[j];
        }
        __syncthreads();
    }
#pragma unroll
    for (int i = 0; i < 4; i++) {
        int m = m0 + ty * 4 + i;
#pragma unroll
        for (int j = 0; j < 8; j++) {
            int o = tx * 8 + j;
            g_qh[m * HID + o] = __float2half_rn(acc[i][j] + bq[o]);
        }
    }
}

// ---------------- K/V projection with fused 2x2 maxpool (grid.y = which) ------
__global__ void proj_kv_kernel(const float* __restrict__ rois,
                               const float* __restrict__ bk_, const float* __restrict__ bv_) {
    __shared__ float As[16 * 64];
    __shared__ float Bs[16 * 128];
    const int which = blockIdx.y;
    const float* wT   = which ? g_wvT : g_wkT;
    const float* bias = which ? bv_   : bk_;
    const int tid = threadIdx.x;
    const int m0  = blockIdx.x * 64;
    const int ty  = tid >> 4, tx = tid & 15;

    float acc[4][8];
#pragma unroll
    for (int i = 0; i < 4; i++)
#pragma unroll
        for (int j = 0; j < 8; j++) acc[i][j] = 0.f;

    for (int kc = 0; kc < C_IN; kc += 16) {
#pragma unroll
        for (int i = 0; i < 4; i++) {
            int e = tid + i * 256;
            int mm = e & 63, k = e >> 6;
            int m = m0 + mm;
            int n = m / PHW;
            int pp = m - n * PHW;
            int py = pp / 7;
            int px = pp - py * 7;
            const float* src = rois + (n * C_IN + kc + k) * HW + py * 28 + px * 2;
            As[k * 64 + mm] = fmaxf(fmaxf(src[0], src[1]), fmaxf(src[14], src[15]));
        }
#pragma unroll
        for (int i = 0; i < 8; i++) {
            int e = tid + i * 256;
            int nn = e & 127, k = e >> 7;
            Bs[k * 128 + nn] = wT[(kc + k) * HID + nn];
        }
        __syncthreads();
#pragma unroll
        for (int k = 0; k < 16; k++) {
            float4 a  = *(const float4*)&As[k * 64 + ty * 4];
            float4 b0 = *(const float4*)&Bs[k * 128 + tx * 8];
            float4 b1 = *(const float4*)&Bs[k * 128 + tx * 8 + 4];
            float av[4] = {a.x, a.y, a.z, a.w};
            float bv[8] = {b0.x, b0.y, b0.z, b0.w, b1.x, b1.y, b1.z, b1.w};
#pragma unroll
            for (int i = 0; i < 4; i++)
#pragma unroll
                for (int j = 0; j < 8; j++) acc[i][j] += av[i] * bv[j];
        }
        __syncthreads();
    }
#pragma unroll
    for (int i = 0; i < 4; i++) {
        int m = m0 + ty * 4 + i;
        if (which == 0) {
#pragma unroll
            for (int j = 0; j < 8; j++) {
                int o = tx * 8 + j;
                g_kh[m * HID + o] = __float2half_rn(acc[i][j] + bias[o]);
            }
        } else {
            int n = m / PHW;
            int pp = m - n * PHW;
            int bb = n >> 6;
            int key = (n & 63) * PHW + pp;
#pragma unroll
            for (int j = 0; j < 8; j++) {
                int o = tx * 8 + j;
                g_vTh[((size_t)(bb * HID + o)) * NK_B + key] = __float2half_rn(acc[i][j] + bias[o]);
            }
        }
    }
}

// ---------------- fp16 HMMA flash attention (cp.async pipelined) ---------------
// BQ=64/CTA, 4 warps x 16 q-rows; 49 chunks of 64 keys. Running row-max softmax.
// smem (halves): K double buf [2][64][136], Vt [128][72]. P lives in registers.
#define SKH_STRIDE 136                 // halves per K row (68 words: conflict-free)
#define SK_BUF_H   (64 * SKH_STRIDE)   // 8704 halves
#define SVH_STRIDE 72                  // halves per Vt row (36 words)
#define SM_V_H     (2 * SK_BUF_H)      // 17408
#define ATTN_SMEM  ((SM_V_H + 128 * SVH_STRIDE) * 2)   // 53248 bytes

__global__ void __launch_bounds__(128, 2) attn_mma_kernel() {
    extern __shared__ __half smh[];
    __half* sK  = smh;
    __half* sVt = smh + SM_V_H;
    const uint32_t sKa  = smem_u32(sK);
    const uint32_t sVta = smem_u32(sVt);

    const int tid  = threadIdx.x;
    const int warp = tid >> 5;
    const int lane = tid & 31;
    const int gr   = lane >> 2;
    const int tg   = lane & 3;
    const int b    = blockIdx.y;
    const int q0   = blockIdx.x * 64;
    const int qrow = warp * 16;

    // ---- Q fragments straight from global (one time) ----
    const __half* qb = g_qh + (size_t)(b * NQ_B + q0 + qrow) * HID;
    uint32_t qf[8][4];
#pragma unroll
    for (int ks = 0; ks < 8; ks++) {
        qf[ks][0] = *(const uint32_t*)(qb + (size_t)gr * HID + ks * 16 + 2 * tg);
        qf[ks][1] = *(const uint32_t*)(qb + (size_t)(gr + 8) * HID + ks * 16 + 2 * tg);
        qf[ks][2] = *(const uint32_t*)(qb + (size_t)gr * HID + ks * 16 + 2 * tg + 8);
        qf[ks][3] = *(const uint32_t*)(qb + (size_t)(gr + 8) * HID + ks * 16 + 2 * tg + 8);
    }

    const __half* kb0 = g_kh + (size_t)(b * NK_B) * HID;
    const __half* vb0 = g_vTh + (size_t)(b * HID) * NK_B;

    // prefetch K[0] (group), V[0] (group)
#pragma unroll
    for (int i = 0; i < 8; i++) {
        int e = tid + i * 128;
        int row = e >> 4;
        int c   = e & 15;
        cpasync16(sKa + row * (SKH_STRIDE * 2) + c * 16, kb0 + (size_t)row * HID + c * 8);
    }
    CP_COMMIT();
#pragma unroll
    for (int i = 0; i < 8; i++) {
        int e = tid + i * 128;
        int row = e >> 3;
        int c   = e & 7;
        cpasync16(sVta + row * (SVH_STRIDE * 2) + c * 16, vb0 + (size_t)row * NK_B + c * 8);
    }
    CP_COMMIT();

    float y[16][4];
#pragma unroll
    for (int nt = 0; nt < 16; nt++)
#pragma unroll
        for (int j = 0; j < 4; j++) y[nt][j] = 0.f;
    float m0 = -INFINITY, m1 = -INFINITY;
    float lsum0 = 0.f, lsum1 = 0.f;

    for (int kc = 0; kc < 49; kc++) {
        CP_WAIT(1);           // K[kc] landed
        __syncthreads();
        const __half* sKb = sK + (kc & 1) * SK_BUF_H;

        if (kc < 48) {        // prefetch K[kc+1] into other buffer
            const __half* kb = kb0 + (size_t)((kc + 1) * 64) * HID;
            uint32_t dstb = sKa + ((kc + 1) & 1) * (SK_BUF_H * 2);
#pragma unroll
            for (int i = 0; i < 8; i++) {
                int e = tid + i * 128;
                int row = e >> 4;
                int c   = e & 15;
                cpasync16(dstb + row * (SKH_STRIDE * 2) + c * 16, kb + (size_t)row * HID + c * 8);
            }
            CP_COMMIT();
        }

        // ---- S = Q K^T : m16 x n64 per warp, k128 in 8 steps ----
        float s[8][4];
#pragma unroll
        for (int nt = 0; nt < 8; nt++)
#pragma unroll
            for (int j = 0; j < 4; j++) s[nt][j] = 0.f;
#pragma unroll
        for (int ks = 0; ks < 8; ks++) {
#pragma unroll
            for (int nt = 0; nt < 8; nt++) {
                uint32_t b0 = *(const uint32_t*)&sKb[(nt * 8 + gr) * SKH_STRIDE + ks * 16 + 2 * tg];
                uint32_t b1 = *(const uint32_t*)&sKb[(nt * 8 + gr) * SKH_STRIDE + ks * 16 + 2 * tg + 8];
                mma_f16(s[nt][0], s[nt][1], s[nt][2], s[nt][3],
                        qf[ks][0], qf[ks][1], qf[ks][2], qf[ks][3], b0, b1);
            }
        }

        // ---- running row max, rescale, exp, pack P into A-fragments ----
        float mx0 = -INFINITY, mx1 = -INFINITY;
#pragma unroll
        for (int nt = 0; nt < 8; nt++) {
            mx0 = fmaxf(mx0, fmaxf(s[nt][0], s[nt][1]));
            mx1 = fmaxf(mx1, fmaxf(s[nt][2], s[nt][3]));
        }
        mx0 = fmaxf(mx0, __shfl_xor_sync(0xffffffffu, mx0, 1));
        mx0 = fmaxf(mx0, __shfl_xor_sync(0xffffffffu, mx0, 2));
        mx1 = fmaxf(mx1, __shfl_xor_sync(0xffffffffu, mx1, 1));
        mx1 = fmaxf(mx1, __shfl_xor_sync(0xffffffffu, mx1, 2));
        float mn0 = fmaxf(m0, mx0);
        float mn1 = fmaxf(m1, mx1);
        float corr0 = __expf(m0 - mn0);
        float corr1 = __expf(m1 - mn1);
        m0 = mn0; m1 = mn1;
        lsum0 *= corr0; lsum1 *= corr1;
#pragma unroll
        for (int nt = 0; nt < 16; nt++) {
            y[nt][0] *= corr0; y[nt][1] *= corr0;
            y[nt][2] *= corr1; y[nt][3] *= corr1;
        }

        uint32_t pa[4][4];
#pragma unroll
        for (int nt = 0; nt < 8; nt++) {
            float p0 = __expf(s[nt][0] - m0);
            float p1 = __expf(s[nt][1] - m0);
            float p2 = __expf(s[nt][2] - m1);
            float p3 = __expf(s[nt][3] - m1);
            lsum0 += p0 + p1;
            lsum1 += p2 + p3;
            __half2 h01 = __floats2half2_rn(p0, p1);
            __half2 h23 = __floats2half2_rn(p2, p3);
            int kp = nt >> 1;
            if ((nt & 1) == 0) {
                pa[kp][0] = *(uint32_t*)&h01;
                pa[kp][1] = *(uint32_t*)&h23;
            } else {
                pa[kp][2] = *(uint32_t*)&h01;
                pa[kp][3] = *(uint32_t*)&h23;
            }
        }

        if (kc < 48) { CP_WAIT(1); } else { CP_WAIT(0); }   // V[kc] landed
        __syncthreads();

        // ---- Y += P V : m16 x n128, k64 in 4 steps ----
#pragma unroll
        for (int ks = 0; ks < 4; ks++) {
#pragma unroll
            for (int nt = 0; nt < 16; nt++) {
                uint32_t b0 = *(const uint32_t*)&sVt[(nt * 8 + gr) * SVH_STRIDE + ks * 16 + 2 * tg];
                uint32_t b1 = *(const uint32_t*)&sVt[(nt * 8 + gr) * SVH_STRIDE + ks * 16 + 2 * tg + 8];
                mma_f16(y[nt][0], y[nt][1], y[nt][2], y[nt][3],
                        pa[ks][0], pa[ks][1], pa[ks][2], pa[ks][3], b0, b1);
            }
        }

        __syncthreads();   // V buffer free
        if (kc < 48) {
            const __half* vb = vb0 + (kc + 1) * 64;
#pragma unroll
            for (int i = 0; i < 8; i++) {
                int e = tid + i * 128;
                int row = e >> 3;
                int c   = e & 7;
                cpasync16(sVta + row * (SVH_STRIDE * 2) + c * 16, vb + (size_t)row * NK_B + c * 8);
            }
            CP_COMMIT();
        }
    }

    // reduce rowsums across 4 lanes sharing a row
#pragma unroll
    for (int off = 1; off < 4; off <<= 1) {
        lsum0 += __shfl_xor_sync(0xffffffffu, lsum0, off);
        lsum1 += __shfl_xor_sync(0xffffffffu, lsum1, off);
    }
    const float inv0 = 1.0f / lsum0;
    const float inv1 = 1.0f / lsum1;

    float* y0 = g_y + (size_t)(b * NQ_B + q0 + qrow + gr) * HID;
    float* y1 = g_y + (size_t)(b * NQ_B + q0 + qrow + gr + 8) * HID;
#pragma unroll
    for (int nt = 0; nt < 16; nt++) {
        *(float2*)(y0 + nt * 8 + 2 * tg) = make_float2(y[nt][0] * inv0, y[nt][1] * inv0);
        *(float2*)(y1 + nt * 8 + 2 * tg) = make_float2(y[nt][2] * inv1, y[nt][3] * inv1);
    }
}

// ---------------- epilogue: out = rois + Y * wre^T + bre ----------------------
__global__ void epilogue_kernel(const float* __restrict__ rois, const float* __restrict__ bre,
                                float* __restrict__ out) {
    __shared__ float As[16 * 68];
    __shared__ float Bs[16 * 128];
    const int tid = threadIdx.x;
    const int m0  = blockIdx.x * 64;
    const int n0  = blockIdx.y * 128;
    const int ty  = tid >> 4, tx = tid & 15;

    float acc[4][8];
#pragma unroll
    for (int i = 0; i < 4; i++)
#pragma unroll
        for (int j = 0; j < 8; j++) acc[i][j] = 0.f;

    const int mm = tid >> 2;
    const int kq = tid & 3;
    for (int kc = 0; kc < HID; kc += 16) {
        float4 a = *(const float4*)&g_y[(size_t)(m0 + mm) * HID + kc + kq * 4];
        As[(kq * 4 + 0) * 68 + mm] = a.x;
        As[(kq * 4 + 1) * 68 + mm] = a.y;
        As[(kq * 4 + 2) * 68 + mm] = a.z;
        As[(kq * 4 + 3) * 68 + mm] = a.w;
#pragma unroll
        for (int i = 0; i < 8; i++) {
            int e = tid + i * 256;
            int nn = e & 127, k = e >> 7;
            Bs[k * 128 + nn] = g_wreT[(kc + k) * C_IN + n0 + nn];
        }
        __syncthreads();
#pragma unroll
        for (int k = 0; k < 16; k++) {
            float4 av4 = *(const float4*)&As[k * 68 + ty * 4];
            float4 b0  = *(const float4*)&Bs[k * 128 + tx * 8];
            float4 b1  = *(const float4*)&Bs[k * 128 + tx * 8 + 4];
            float av[4] = {av4.x, av4.y, av4.z, av4.w};
            float bv[8] = {b0.x, b0.y, b0.z, b0.w, b1.x, b1.y, b1.z, b1.w};
#pragma unroll
            for (int i = 0; i < 4; i++)
#pragma unroll
                for (int j = 0; j < 8; j++) acc[i][j] += av[i] * bv[j];
        }
        __syncthreads();
    }
#pragma unroll
    for (int i = 0; i < 4; i++) {
        int m = m0 + ty * 4 + i;
        int n = m / HW;
        int p = m - n * HW;
#pragma unroll
        for (int j = 0; j < 8; j++) {
            int co = n0 + tx * 8 + j;
            int idx = (n * C_IN + co) * HW + p;
            out[idx] = rois[idx] + acc[i][j] + bre[co];
        }
    }
}

// ---------------- launch ------------------------------------------------------
extern "C" void kernel_launch(void* const* d_in, const int* in_sizes, int n_in,
                              void* d_out, int out_size) {
    const float* rois = (const float*)d_in[0];
    const float* wq  = (const float*)d_in[2];
    const float* bq  = (const float*)d_in[3];
    const float* wk  = (const float*)d_in[4];
    const float* bk  = (const float*)d_in[5];
    const float* wv  = (const float*)d_in[6];
    const float* bv  = (const float*)d_in[7];
    const float* wre = (const float*)d_in[8];
    const float* bre = (const float*)d_in[9];
    float* out = (float*)d_out;

    cudaFuncSetAttribute(attn_mma_kernel, cudaFuncAttributeMaxDynamicSharedMemorySize, ATTN_SMEM);

    prep_weights<<<64, 512>>>(wq, wk, wv, wre);
    proj_q_kernel<<<392, 256>>>(rois, bq);
    proj_kv_kernel<<<dim3(98, 2), 256>>>(rois, bk, bv);
    attn_mma_kernel<<<dim3(196, 2), 128, ATTN_SMEM>>>();
    epilogue_kernel<<<dim3(392, 2), 256>>>(rois, bre, out);
}

// round 7
// speedup vs baseline: 5.2276x; 1.2387x over previous
#include <cuda_runtime.h>
#include <cuda_fp16.h>
#include <math.h>
#include <stdint.h>

#define C_IN 256
#define HID  128
#define HW   196      // 14*14
#define PHW  49       // 7*7
#define MQ   25088    // 128 * 196
#define MK   6272     // 128 * 49
#define NQ_B 12544
#define NK_B 3136

// ---------------- scratch (device globals) ------------------------------------
__device__ __align__(256) __half g_Aq[MQ * C_IN];        // roisT fp16 [m][c]
__device__ __align__(256) __half g_Ap[MK * C_IN];        // pooled roisT fp16
__device__ __align__(256) __half g_qh[MQ * HID];
__device__ __align__(256) __half g_kh[MK * HID];
__device__ __align__(256) __half g_vTh[2 * HID * NK_B];  // [b][h][key]
__device__ __align__(256) __half g_yh[MQ * HID];
__device__ __align__(256) __half g_wqh[HID * C_IN];
__device__ __align__(256) __half g_wkh[HID * C_IN];
__device__ __align__(256) __half g_wvh[HID * C_IN];
__device__ __align__(256) __half g_wreh[C_IN * HID];

// ---------------- PTX helpers --------------------------------------------------
__device__ __forceinline__ void mma_f16(float& d0, float& d1, float& d2, float& d3,
                                        uint32_t a0, uint32_t a1, uint32_t a2, uint32_t a3,
                                        uint32_t b0, uint32_t b1) {
    asm volatile(
        "mma.sync.aligned.m16n8k16.row.col.f32.f16.f16.f32 "
        "{%0,%1,%2,%3}, {%4,%5,%6,%7}, {%8,%9}, {%0,%1,%2,%3};"
        : "+f"(d0), "+f"(d1), "+f"(d2), "+f"(d3)
        : "r"(a0), "r"(a1), "r"(a2), "r"(a3), "r"(b0), "r"(b1));
}
__device__ __forceinline__ uint32_t smem_u32(const void* p) {
    uint32_t a;
    asm("{ .reg .u64 t; cvta.to.shared.u64 t, %1; cvt.u32.u64 %0, t; }" : "=r"(a) : "l"(p));
    return a;
}
__device__ __forceinline__ void cpasync16(uint32_t dst, const void* src) {
    asm volatile("cp.async.cg.shared.global [%0], [%1], 16;" :: "r"(dst), "l"(src));
}
#define CP_COMMIT() asm volatile("cp.async.commit_group;" ::: "memory")
#define CP_WAIT(N)  asm volatile("cp.async.wait_group %0;" :: "n"(N) : "memory")

// ---------------- prep: weights -> fp16 ---------------------------------------
__global__ void prep_weights_h(const float* __restrict__ wq, const float* __restrict__ wk,
                               const float* __restrict__ wv, const float* __restrict__ wre) {
    int t = blockIdx.x * blockDim.x + threadIdx.x;
    if (t < HID * C_IN) {
        g_wqh[t]  = __float2half_rn(wq[t]);
        g_wkh[t]  = __float2half_rn(wk[t]);
        g_wvh[t]  = __float2half_rn(wv[t]);
        g_wreh[t] = __float2half_rn(wre[t]);
    }
}

// ---------------- prep: rois transpose + pool -> fp16 A matrices ---------------
__global__ void prep_rois(const float* __restrict__ rois) {
    __shared__ float t[32][197];
    const int n = blockIdx.x;          // ROI index 0..127
    const int tid = threadIdx.x;

    for (int c0 = 0; c0 < C_IN; c0 += 32) {
        __syncthreads();
        for (int e = tid; e < 32 * HW; e += 256) {
            int ci = e / HW, p = e - ci * HW;
            t[ci][p] = rois[(n * C_IN + c0 + ci) * HW + p];
        }
        __syncthreads();
        // full-res transposed (half2 over channel pairs)
        for (int e = tid; e < HW * 16; e += 256) {
            int p = e >> 4, cp = e & 15;
            __half2 h = __floats2half2_rn(t[2 * cp][p], t[2 * cp + 1][p]);
            ((__half2*)g_Aq)[(size_t)(n * HW + p) * 128 + (c0 >> 1) + cp] = h;
        }
        // pooled transposed
        for (int e = tid; e < PHW * 16; e += 256) {
            int pp = e >> 4, cp = e & 15;
            int py = pp / 7, px = pp - py * 7;
            int base = py * 28 + px * 2;
            float a0 = fmaxf(fmaxf(t[2 * cp][base], t[2 * cp][base + 1]),
                             fmaxf(t[2 * cp][base + 14], t[2 * cp][base + 15]));
            float a1 = fmaxf(fmaxf(t[2 * cp + 1][base], t[2 * cp + 1][base + 1]),
                             fmaxf(t[2 * cp + 1][base + 14], t[2 * cp + 1][base + 15]));
            ((__half2*)g_Ap)[(size_t)(n * PHW + pp) * 128 + (c0 >> 1) + cp] = __floats2half2_rn(a0, a1);
        }
    }
}

// ---------------- fused QKV projection GEMM (fp16 HMMA) -----------------------
// grid.x: [0,196) Q tiles, [196,245) K, [245,294) V. M-tile 128, N=128, K=256.
#define PJ_STRIDE 72                       // halves per A row chunk (64 + 8 pad)
#define PJ_BUF    (128 * PJ_STRIDE)        // halves per buffer
#define PJ_VST    130                      // V transpose stage stride (halves)
#define PJ_SMEM   (2 * PJ_BUF * 2)         // 36864 B

__global__ void __launch_bounds__(256, 4) proj_mma(const float* __restrict__ bq,
                                                   const float* __restrict__ bk,
                                                   const float* __restrict__ bv) {
    extern __shared__ __half psm[];
    const uint32_t psa = smem_u32(psm);

    int bx = blockIdx.x;
    int which, t0;
    if (bx < 196)      { which = 0; t0 = bx; }
    else if (bx < 245) { which = 1; t0 = bx - 196; }
    else               { which = 2; t0 = bx - 245; }
    const __half* A    = which ? g_Ap : g_Aq;
    const __half* W    = which == 0 ? g_wqh : (which == 1 ? g_wkh : g_wvh);
    const float*  bias = which == 0 ? bq    : (which == 1 ? bk    : bv);
    const int m0 = t0 * 128;

    const int tid  = threadIdx.x;
    const int warp = tid >> 5;
    const int lane = tid & 31;
    const int gr   = lane >> 2;
    const int tg   = lane & 3;
    const int qrow = warp * 16;

    // prefetch chunk 0
    {
        const __half* src = A + (size_t)m0 * C_IN;
#pragma unroll
        for (int i = 0; i < 4; i++) {
            int e = tid + i * 256;
            int row = e >> 3, seg = e & 7;
            cpasync16(psa + (row * PJ_STRIDE + seg * 8) * 2, src + (size_t)row * C_IN + seg * 8);
        }
        CP_COMMIT();
    }

    float y[16][4];
#pragma unroll
    for (int nt = 0; nt < 16; nt++)
#pragma unroll
        for (int j = 0; j < 4; j++) y[nt][j] = 0.f;

    for (int kc = 0; kc < 4; kc++) {
        CP_WAIT(0);
        __syncthreads();
        const __half* sA = psm + (kc & 1) * PJ_BUF;
        if (kc < 3) {
            const __half* src = A + (size_t)m0 * C_IN + (kc + 1) * 64;
            uint32_t dstb = psa + ((kc + 1) & 1) * (PJ_BUF * 2);
#pragma unroll
            for (int i = 0; i < 4; i++) {
                int e = tid + i * 256;
                int row = e >> 3, seg = e & 7;
                cpasync16(dstb + (row * PJ_STRIDE + seg * 8) * 2, src + (size_t)row * C_IN + seg * 8);
            }
            CP_COMMIT();
        }
#pragma unroll
        for (int ks = 0; ks < 4; ks++) {
            int k = kc * 64 + ks * 16;
            uint32_t a0 = *(const uint32_t*)&sA[(qrow + gr) * PJ_STRIDE + ks * 16 + 2 * tg];
            uint32_t a1 = *(const uint32_t*)&sA[(qrow + gr + 8) * PJ_STRIDE + ks * 16 + 2 * tg];
            uint32_t a2 = *(const uint32_t*)&sA[(qrow + gr) * PJ_STRIDE + ks * 16 + 2 * tg + 8];
            uint32_t a3 = *(const uint32_t*)&sA[(qrow + gr + 8) * PJ_STRIDE + ks * 16 + 2 * tg + 8];
#pragma unroll
            for (int nt = 0; nt < 16; nt++) {
                int o = nt * 8 + gr;
                uint32_t b0 = *(const uint32_t*)&W[(size_t)o * C_IN + k + 2 * tg];
                uint32_t b1 = *(const uint32_t*)&W[(size_t)o * C_IN + k + 2 * tg + 8];
                mma_f16(y[nt][0], y[nt][1], y[nt][2], y[nt][3], a0, a1, a2, a3, b0, b1);
            }
        }
        __syncthreads();
    }

    if (which < 2) {
        __half* dst = which == 0 ? g_qh : g_kh;
#pragma unroll
        for (int nt = 0; nt < 16; nt++) {
            int o = nt * 8 + 2 * tg;
            float bb0 = bias[o], bb1 = bias[o + 1];
            *(__half2*)&dst[(size_t)(m0 + qrow + gr) * HID + o] =
                __floats2half2_rn(y[nt][0] + bb0, y[nt][1] + bb1);
            *(__half2*)&dst[(size_t)(m0 + qrow + gr + 8) * HID + o] =
                __floats2half2_rn(y[nt][2] + bb0, y[nt][3] + bb1);
        }
    } else {
        // V: stage [key][h] in smem, then write transposed to g_vTh[b][h][key]
        __half* sV = psm;
#pragma unroll
        for (int nt = 0; nt < 16; nt++) {
            int o = nt * 8 + 2 * tg;
            float bb0 = bias[o], bb1 = bias[o + 1];
            sV[(qrow + gr) * PJ_VST + o]         = __float2half_rn(y[nt][0] + bb0);
            sV[(qrow + gr) * PJ_VST + o + 1]     = __float2half_rn(y[nt][1] + bb1);
            sV[(qrow + gr + 8) * PJ_VST + o]     = __float2half_rn(y[nt][2] + bb0);
            sV[(qrow + gr + 8) * PJ_VST + o + 1] = __float2half_rn(y[nt][3] + bb1);
        }
        __syncthreads();
#pragma unroll
        for (int i = 0; i < 64; i++) {
            int e = tid + i * 256;
            int h = e >> 7, kk = e & 127;
            int m = m0 + kk;
            int bb = (m >= NK_B) ? 1 : 0;
            int key = m - bb * NK_B;
            g_vTh[(size_t)(bb * HID + h) * NK_B + key] = sV[kk * PJ_VST + h];
        }
    }
}

// ---------------- fp16 HMMA flash attention (unchanged core; fp16 Y out) -------
#define SKH_STRIDE 136
#define SK_BUF_H   (64 * SKH_STRIDE)
#define SVH_STRIDE 72
#define SM_V_H     (2 * SK_BUF_H)
#define ATTN_SMEM  ((SM_V_H + 128 * SVH_STRIDE) * 2)

__global__ void __launch_bounds__(128, 2) attn_mma_kernel() {
    extern __shared__ __half smh[];
    __half* sK  = smh;
    __half* sVt = smh + SM_V_H;
    const uint32_t sKa  = smem_u32(sK);
    const uint32_t sVta = smem_u32(sVt);

    const int tid  = threadIdx.x;
    const int warp = tid >> 5;
    const int lane = tid & 31;
    const int gr   = lane >> 2;
    const int tg   = lane & 3;
    const int b    = blockIdx.y;
    const int q0   = blockIdx.x * 64;
    const int qrow = warp * 16;

    const __half* qb = g_qh + (size_t)(b * NQ_B + q0 + qrow) * HID;
    uint32_t qf[8][4];
#pragma unroll
    for (int ks = 0; ks < 8; ks++) {
        qf[ks][0] = *(const uint32_t*)(qb + (size_t)gr * HID + ks * 16 + 2 * tg);
        qf[ks][1] = *(const uint32_t*)(qb + (size_t)(gr + 8) * HID + ks * 16 + 2 * tg);
        qf[ks][2] = *(const uint32_t*)(qb + (size_t)gr * HID + ks * 16 + 2 * tg + 8);
        qf[ks][3] = *(const uint32_t*)(qb + (size_t)(gr + 8) * HID + ks * 16 + 2 * tg + 8);
    }

    const __half* kb0 = g_kh + (size_t)(b * NK_B) * HID;
    const __half* vb0 = g_vTh + (size_t)(b * HID) * NK_B;

#pragma unroll
    for (int i = 0; i < 8; i++) {
        int e = tid + i * 128;
        int row = e >> 4, c = e & 15;
        cpasync16(sKa + row * (SKH_STRIDE * 2) + c * 16, kb0 + (size_t)row * HID + c * 8);
    }
    CP_COMMIT();
#pragma unroll
    for (int i = 0; i < 8; i++) {
        int e = tid + i * 128;
        int row = e >> 3, c = e & 7;
        cpasync16(sVta + row * (SVH_STRIDE * 2) + c * 16, vb0 + (size_t)row * NK_B + c * 8);
    }
    CP_COMMIT();

    float y[16][4];
#pragma unroll
    for (int nt = 0; nt < 16; nt++)
#pragma unroll
        for (int j = 0; j < 4; j++) y[nt][j] = 0.f;
    float m0 = -INFINITY, m1 = -INFINITY;
    float lsum0 = 0.f, lsum1 = 0.f;

    for (int kc = 0; kc < 49; kc++) {
        CP_WAIT(1);
        __syncthreads();
        const __half* sKb = sK + (kc & 1) * SK_BUF_H;

        if (kc < 48) {
            const __half* kb = kb0 + (size_t)((kc + 1) * 64) * HID;
            uint32_t dstb = sKa + ((kc + 1) & 1) * (SK_BUF_H * 2);
#pragma unroll
            for (int i = 0; i < 8; i++) {
                int e = tid + i * 128;
                int row = e >> 4, c = e & 15;
                cpasync16(dstb + row * (SKH_STRIDE * 2) + c * 16, kb + (size_t)row * HID + c * 8);
            }
            CP_COMMIT();
        }

        float s[8][4];
#pragma unroll
        for (int nt = 0; nt < 8; nt++)
#pragma unroll
            for (int j = 0; j < 4; j++) s[nt][j] = 0.f;
#pragma unroll
        for (int ks = 0; ks < 8; ks++) {
#pragma unroll
            for (int nt = 0; nt < 8; nt++) {
                uint32_t b0 = *(const uint32_t*)&sKb[(nt * 8 + gr) * SKH_STRIDE + ks * 16 + 2 * tg];
                uint32_t b1 = *(const uint32_t*)&sKb[(nt * 8 + gr) * SKH_STRIDE + ks * 16 + 2 * tg + 8];
                mma_f16(s[nt][0], s[nt][1], s[nt][2], s[nt][3],
                        qf[ks][0], qf[ks][1], qf[ks][2], qf[ks][3], b0, b1);
            }
        }

        float mx0 = -INFINITY, mx1 = -INFINITY;
#pragma unroll
        for (int nt = 0; nt < 8; nt++) {
            mx0 = fmaxf(mx0, fmaxf(s[nt][0], s[nt][1]));
            mx1 = fmaxf(mx1, fmaxf(s[nt][2], s[nt][3]));
        }
        mx0 = fmaxf(mx0, __shfl_xor_sync(0xffffffffu, mx0, 1));
        mx0 = fmaxf(mx0, __shfl_xor_sync(0xffffffffu, mx0, 2));
        mx1 = fmaxf(mx1, __shfl_xor_sync(0xffffffffu, mx1, 1));
        mx1 = fmaxf(mx1, __shfl_xor_sync(0xffffffffu, mx1, 2));
        float mn0 = fmaxf(m0, mx0);
        float mn1 = fmaxf(m1, mx1);
        float corr0 = __expf(m0 - mn0);
        float corr1 = __expf(m1 - mn1);
        m0 = mn0; m1 = mn1;
        lsum0 *= corr0; lsum1 *= corr1;
#pragma unroll
        for (int nt = 0; nt < 16; nt++) {
            y[nt][0] *= corr0; y[nt][1] *= corr0;
            y[nt][2] *= corr1; y[nt][3] *= corr1;
        }

        uint32_t pa[4][4];
#pragma unroll
        for (int nt = 0; nt < 8; nt++) {
            float p0 = __expf(s[nt][0] - m0);
            float p1 = __expf(s[nt][1] - m0);
            float p2 = __expf(s[nt][2] - m1);
            float p3 = __expf(s[nt][3] - m1);
            lsum0 += p0 + p1;
            lsum1 += p2 + p3;
            __half2 h01 = __floats2half2_rn(p0, p1);
            __half2 h23 = __floats2half2_rn(p2, p3);
            int kp = nt >> 1;
            if ((nt & 1) == 0) { pa[kp][0] = *(uint32_t*)&h01; pa[kp][1] = *(uint32_t*)&h23; }
            else               { pa[kp][2] = *(uint32_t*)&h01; pa[kp][3] = *(uint32_t*)&h23; }
        }

        if (kc < 48) { CP_WAIT(1); } else { CP_WAIT(0); }
        __syncthreads();

#pragma unroll
        for (int ks = 0; ks < 4; ks++) {
#pragma unroll
            for (int nt = 0; nt < 16; nt++) {
                uint32_t b0 = *(const uint32_t*)&sVt[(nt * 8 + gr) * SVH_STRIDE + ks * 16 + 2 * tg];
                uint32_t b1 = *(const uint32_t*)&sVt[(nt * 8 + gr) * SVH_STRIDE + ks * 16 + 2 * tg + 8];
                mma_f16(y[nt][0], y[nt][1], y[nt][2], y[nt][3],
                        pa[ks][0], pa[ks][1], pa[ks][2], pa[ks][3], b0, b1);
            }
        }

        __syncthreads();
        if (kc < 48) {
            const __half* vb = vb0 + (kc + 1) * 64;
#pragma unroll
            for (int i = 0; i < 8; i++) {
                int e = tid + i * 128;
                int row = e >> 3, c = e & 7;
                cpasync16(sVta + row * (SVH_STRIDE * 2) + c * 16, vb + (size_t)row * NK_B + c * 8);
            }
            CP_COMMIT();
        }
    }

#pragma unroll
    for (int off = 1; off < 4; off <<= 1) {
        lsum0 += __shfl_xor_sync(0xffffffffu, lsum0, off);
        lsum1 += __shfl_xor_sync(0xffffffffu, lsum1, off);
    }
    const float inv0 = 1.0f / lsum0;
    const float inv1 = 1.0f / lsum1;

    __half* y0 = g_yh + (size_t)(b * NQ_B + q0 + qrow + gr) * HID;
    __half* y1 = g_yh + (size_t)(b * NQ_B + q0 + qrow + gr + 8) * HID;
#pragma unroll
    for (int nt = 0; nt < 16; nt++) {
        *(__half2*)(y0 + nt * 8 + 2 * tg) = __floats2half2_rn(y[nt][0] * inv0, y[nt][1] * inv0);
        *(__half2*)(y1 + nt * 8 + 2 * tg) = __floats2half2_rn(y[nt][2] * inv1, y[nt][3] * inv1);
    }
}

// ---------------- epilogue GEMM: out = rois + Y*wre^T + bre (fp16 HMMA) --------
// grid (196, 2): m-tile 128, n-tile 128, K=128.
#define EP_ASTRIDE 136                 // halves
#define EP_DSTRIDE 129                 // floats
#define EP_SMEM (128 * EP_DSTRIDE * 4) // 66048 B (>= A stage 34.8KB)

__global__ void __launch_bounds__(256, 2) ep_mma(const float* __restrict__ rois,
                                                 const float* __restrict__ bre,
                                                 float* __restrict__ out) {
    extern __shared__ char esm[];
    __half* sA = (__half*)esm;
    float*  sD = (float*)esm;
    const uint32_t sAa = smem_u32(sA);

    const int tid  = threadIdx.x;
    const int warp = tid >> 5;
    const int lane = tid & 31;
    const int gr   = lane >> 2;
    const int tg   = lane & 3;
    const int m0   = blockIdx.x * 128;
    const int n0   = blockIdx.y * 128;
    const int qrow = warp * 16;

    // stage A = Y tile [128][128] fp16
    {
        const __half* src = g_yh + (size_t)m0 * HID;
#pragma unroll
        for (int i = 0; i < 8; i++) {
            int e = tid + i * 256;
            int row = e >> 4, seg = e & 15;
            cpasync16(sAa + (row * EP_ASTRIDE + seg * 8) * 2, src + (size_t)row * HID + seg * 8);
        }
        CP_COMMIT();
        CP_WAIT(0);
        __syncthreads();
    }

    float y[16][4];
#pragma unroll
    for (int nt = 0; nt < 16; nt++)
#pragma unroll
        for (int j = 0; j < 4; j++) y[nt][j] = 0.f;

#pragma unroll
    for (int ks = 0; ks < 8; ks++) {
        int k = ks * 16;
        uint32_t a0 = *(const uint32_t*)&sA[(qrow + gr) * EP_ASTRIDE + k + 2 * tg];
        uint32_t a1 = *(const uint32_t*)&sA[(qrow + gr + 8) * EP_ASTRIDE + k + 2 * tg];
        uint32_t a2 = *(const uint32_t*)&sA[(qrow + gr) * EP_ASTRIDE + k + 2 * tg + 8];
        uint32_t a3 = *(const uint32_t*)&sA[(qrow + gr + 8) * EP_ASTRIDE + k + 2 * tg + 8];
#pragma unroll
        for (int nt = 0; nt < 16; nt++) {
            int o = n0 + nt * 8 + gr;
            uint32_t b0 = *(const uint32_t*)&g_wreh[(size_t)o * HID + k + 2 * tg];
            uint32_t b1 = *(const uint32_t*)&g_wreh[(size_t)o * HID + k + 2 * tg + 8];
            mma_f16(y[nt][0], y[nt][1], y[nt][2], y[nt][3], a0, a1, a2, a3, b0, b1);
        }
    }
    __syncthreads();   // done reading sA; sD overlaps

    // stage D in smem (pad-129 -> conflict-free column reads)
#pragma unroll
    for (int nt = 0; nt < 16; nt++) {
        int o = nt * 8 + 2 * tg;
        sD[(qrow + gr) * EP_DSTRIDE + o]         = y[nt][0];
        sD[(qrow + gr) * EP_DSTRIDE + o + 1]     = y[nt][1];
        sD[(qrow + gr + 8) * EP_DSTRIDE + o]     = y[nt][2];
        sD[(qrow + gr + 8) * EP_DSTRIDE + o + 1] = y[nt][3];
    }
    __syncthreads();

    // coalesced residual add + store: m-contiguous per o
#pragma unroll 4
    for (int i = 0; i < 64; i++) {
        int e = tid + i * 256;
        int o = e >> 7, ml = e & 127;
        int m = m0 + ml;
        int n = m / HW;
        int p = m - n * HW;
        int co = n0 + o;
        size_t idx = (size_t)(n * C_IN + co) * HW + p;
        out[idx] = rois[idx] + sD[ml * EP_DSTRIDE + o] + bre[co];
    }
}

// ---------------- launch ------------------------------------------------------
extern "C" void kernel_launch(void* const* d_in, const int* in_sizes, int n_in,
                              void* d_out, int out_size) {
    const float* rois = (const float*)d_in[0];
    const float* wq  = (const float*)d_in[2];
    const float* bq  = (const float*)d_in[3];
    const float* wk  = (const float*)d_in[4];
    const float* bk  = (const float*)d_in[5];
    const float* wv  = (const float*)d_in[6];
    const float* bv  = (const float*)d_in[7];
    const float* wre = (const float*)d_in[8];
    const float* bre = (const float*)d_in[9];
    float* out = (float*)d_out;

    cudaFuncSetAttribute(attn_mma_kernel, cudaFuncAttributeMaxDynamicSharedMemorySize, ATTN_SMEM);
    cudaFuncSetAttribute(proj_mma, cudaFuncAttributeMaxDynamicSharedMemorySize, PJ_SMEM);
    cudaFuncSetAttribute(ep_mma, cudaFuncAttributeMaxDynamicSharedMemorySize, EP_SMEM);

    prep_weights_h<<<128, 256>>>(wq, wk, wv, wre);
    prep_rois<<<128, 256>>>(rois);
    proj_mma<<<294, 256, PJ_SMEM>>>(bq, bk, bv);
    attn_mma_kernel<<<dim3(196, 2), 128, ATTN_SMEM>>>();
    ep_mma<<<dim3(196, 2), 256, EP_SMEM>>>(rois, bre, out);
}

// round 8
// speedup vs baseline: 6.3718x; 1.2189x over previous
#include <cuda_runtime.h>
#include <cuda_fp16.h>
#include <math.h>
#include <stdint.h>

#define C_IN 256
#define HID  128
#define HW   196      // 14*14
#define PHW  49       // 7*7
#define MQ   25088    // 128 * 196
#define MK   6272     // 128 * 49
#define NQ_B 12544
#define NK_B 3136

// ---------------- scratch (device globals) ------------------------------------
__device__ __align__(256) __half g_Aq[MQ * C_IN];        // roisT fp16 [m][c]
__device__ __align__(256) __half g_Ap[MK * C_IN];        // pooled roisT fp16
__device__ __align__(256) __half g_qh[MQ * HID];
__device__ __align__(256) __half g_kh[MK * HID];
__device__ __align__(256) __half g_vTh[2 * HID * NK_B];  // [b][h][key]
__device__ __align__(256) __half g_yh[MQ * HID];
__device__ __align__(256) __half g_wqh[HID * C_IN];
__device__ __align__(256) __half g_wkh[HID * C_IN];
__device__ __align__(256) __half g_wvh[HID * C_IN];
__device__ __align__(256) __half g_wreh[C_IN * HID];

// ---------------- PTX helpers --------------------------------------------------
__device__ __forceinline__ void mma_f16(float& d0, float& d1, float& d2, float& d3,
                                        uint32_t a0, uint32_t a1, uint32_t a2, uint32_t a3,
                                        uint32_t b0, uint32_t b1) {
    asm volatile(
        "mma.sync.aligned.m16n8k16.row.col.f32.f16.f16.f32 "
        "{%0,%1,%2,%3}, {%4,%5,%6,%7}, {%8,%9}, {%0,%1,%2,%3};"
        : "+f"(d0), "+f"(d1), "+f"(d2), "+f"(d3)
        : "r"(a0), "r"(a1), "r"(a2), "r"(a3), "r"(b0), "r"(b1));
}
__device__ __forceinline__ uint32_t smem_u32(const void* p) {
    uint32_t a;
    asm("{ .reg .u64 t; cvta.to.shared.u64 t, %1; cvt.u32.u64 %0, t; }" : "=r"(a) : "l"(p));
    return a;
}
__device__ __forceinline__ void cpasync16(uint32_t dst, const void* src) {
    asm volatile("cp.async.cg.shared.global [%0], [%1], 16;" :: "r"(dst), "l"(src));
}
#define CP_COMMIT() asm volatile("cp.async.commit_group;" ::: "memory")
#define CP_WAIT(N)  asm volatile("cp.async.wait_group %0;" :: "n"(N) : "memory")

// ---------------- prep: weights -> fp16 ---------------------------------------
__global__ void prep_weights_h(const float* __restrict__ wq, const float* __restrict__ wk,
                               const float* __restrict__ wv, const float* __restrict__ wre) {
    int t = blockIdx.x * blockDim.x + threadIdx.x;
    if (t < HID * C_IN) {
        g_wqh[t]  = __float2half_rn(wq[t]);
        g_wkh[t]  = __float2half_rn(wk[t]);
        g_wvh[t]  = __float2half_rn(wv[t]);
        g_wreh[t] = __float2half_rn(wre[t]);
    }
}

// ---------------- prep: rois transpose + pool -> fp16 A matrices ---------------
__global__ void prep_rois(const float* __restrict__ rois) {
    __shared__ float t[32][197];
    const int n = blockIdx.x;          // ROI index 0..127
    const int tid = threadIdx.x;

    for (int c0 = 0; c0 < C_IN; c0 += 32) {
        __syncthreads();
        for (int e = tid; e < 32 * HW; e += 256) {
            int ci = e / HW, p = e - ci * HW;
            t[ci][p] = rois[(n * C_IN + c0 + ci) * HW + p];
        }
        __syncthreads();
        for (int e = tid; e < HW * 16; e += 256) {
            int p = e >> 4, cp = e & 15;
            __half2 h = __floats2half2_rn(t[2 * cp][p], t[2 * cp + 1][p]);
            ((__half2*)g_Aq)[(size_t)(n * HW + p) * 128 + (c0 >> 1) + cp] = h;
        }
        for (int e = tid; e < PHW * 16; e += 256) {
            int pp = e >> 4, cp = e & 15;
            int py = pp / 7, px = pp - py * 7;
            int base = py * 28 + px * 2;
            float a0 = fmaxf(fmaxf(t[2 * cp][base], t[2 * cp][base + 1]),
                             fmaxf(t[2 * cp][base + 14], t[2 * cp][base + 15]));
            float a1 = fmaxf(fmaxf(t[2 * cp + 1][base], t[2 * cp + 1][base + 1]),
                             fmaxf(t[2 * cp + 1][base + 14], t[2 * cp + 1][base + 15]));
            ((__half2*)g_Ap)[(size_t)(n * PHW + pp) * 128 + (c0 >> 1) + cp] = __floats2half2_rn(a0, a1);
        }
    }
}

// ---------------- fused QKV projection GEMM (fp16 HMMA) -----------------------
#define PJ_STRIDE 72
#define PJ_BUF    (128 * PJ_STRIDE)
#define PJ_VST    130
#define PJ_SMEM   (2 * PJ_BUF * 2)

__global__ void __launch_bounds__(256, 4) proj_mma(const float* __restrict__ bq,
                                                   const float* __restrict__ bk,
                                                   const float* __restrict__ bv) {
    extern __shared__ __half psm[];
    const uint32_t psa = smem_u32(psm);

    int bx = blockIdx.x;
    int which, t0;
    if (bx < 196)      { which = 0; t0 = bx; }
    else if (bx < 245) { which = 1; t0 = bx - 196; }
    else               { which = 2; t0 = bx - 245; }
    const __half* A    = which ? g_Ap : g_Aq;
    const __half* W    = which == 0 ? g_wqh : (which == 1 ? g_wkh : g_wvh);
    const float*  bias = which == 0 ? bq    : (which == 1 ? bk    : bv);
    const int m0 = t0 * 128;

    const int tid  = threadIdx.x;
    const int warp = tid >> 5;
    const int lane = tid & 31;
    const int gr   = lane >> 2;
    const int tg   = lane & 3;
    const int qrow = warp * 16;

    {
        const __half* src = A + (size_t)m0 * C_IN;
#pragma unroll
        for (int i = 0; i < 4; i++) {
            int e = tid + i * 256;
            int row = e >> 3, seg = e & 7;
            cpasync16(psa + (row * PJ_STRIDE + seg * 8) * 2, src + (size_t)row * C_IN + seg * 8);
        }
        CP_COMMIT();
    }

    float y[16][4];
#pragma unroll
    for (int nt = 0; nt < 16; nt++)
#pragma unroll
        for (int j = 0; j < 4; j++) y[nt][j] = 0.f;

    for (int kc = 0; kc < 4; kc++) {
        CP_WAIT(0);
        __syncthreads();
        const __half* sA = psm + (kc & 1) * PJ_BUF;
        if (kc < 3) {
            const __half* src = A + (size_t)m0 * C_IN + (kc + 1) * 64;
            uint32_t dstb = psa + ((kc + 1) & 1) * (PJ_BUF * 2);
#pragma unroll
            for (int i = 0; i < 4; i++) {
                int e = tid + i * 256;
                int row = e >> 3, seg = e & 7;
                cpasync16(dstb + (row * PJ_STRIDE + seg * 8) * 2, src + (size_t)row * C_IN + seg * 8);
            }
            CP_COMMIT();
        }
#pragma unroll
        for (int ks = 0; ks < 4; ks++) {
            int k = kc * 64 + ks * 16;
            uint32_t a0 = *(const uint32_t*)&sA[(qrow + gr) * PJ_STRIDE + ks * 16 + 2 * tg];
            uint32_t a1 = *(const uint32_t*)&sA[(qrow + gr + 8) * PJ_STRIDE + ks * 16 + 2 * tg];
            uint32_t a2 = *(const uint32_t*)&sA[(qrow + gr) * PJ_STRIDE + ks * 16 + 2 * tg + 8];
            uint32_t a3 = *(const uint32_t*)&sA[(qrow + gr + 8) * PJ_STRIDE + ks * 16 + 2 * tg + 8];
#pragma unroll
            for (int nt = 0; nt < 16; nt++) {
                int o = nt * 8 + gr;
                uint32_t b0 = *(const uint32_t*)&W[(size_t)o * C_IN + k + 2 * tg];
                uint32_t b1 = *(const uint32_t*)&W[(size_t)o * C_IN + k + 2 * tg + 8];
                mma_f16(y[nt][0], y[nt][1], y[nt][2], y[nt][3], a0, a1, a2, a3, b0, b1);
            }
        }
        __syncthreads();
    }

    if (which < 2) {
        __half* dst = which == 0 ? g_qh : g_kh;
#pragma unroll
        for (int nt = 0; nt < 16; nt++) {
            int o = nt * 8 + 2 * tg;
            float bb0 = bias[o], bb1 = bias[o + 1];
            *(__half2*)&dst[(size_t)(m0 + qrow + gr) * HID + o] =
                __floats2half2_rn(y[nt][0] + bb0, y[nt][1] + bb1);
            *(__half2*)&dst[(size_t)(m0 + qrow + gr + 8) * HID + o] =
                __floats2half2_rn(y[nt][2] + bb0, y[nt][3] + bb1);
        }
    } else {
        __half* sV = psm;
#pragma unroll
        for (int nt = 0; nt < 16; nt++) {
            int o = nt * 8 + 2 * tg;
            float bb0 = bias[o], bb1 = bias[o + 1];
            sV[(qrow + gr) * PJ_VST + o]         = __float2half_rn(y[nt][0] + bb0);
            sV[(qrow + gr) * PJ_VST + o + 1]     = __float2half_rn(y[nt][1] + bb1);
            sV[(qrow + gr + 8) * PJ_VST + o]     = __float2half_rn(y[nt][2] + bb0);
            sV[(qrow + gr + 8) * PJ_VST + o + 1] = __float2half_rn(y[nt][3] + bb1);
        }
        __syncthreads();
#pragma unroll
        for (int i = 0; i < 64; i++) {
            int e = tid + i * 256;
            int h = e >> 7, kk = e & 127;
            int m = m0 + kk;
            int bb = (m >= NK_B) ? 1 : 0;
            int key = m - bb * NK_B;
            g_vTh[(size_t)(bb * HID + h) * NK_B + key] = sV[kk * PJ_VST + h];
        }
    }
}

// ---------------- fp16 HMMA flash attention (1 barrier/chunk) ------------------
// K double buf [2][64][136]h, V double buf [2][128][72]h. One cp.async group and
// one __syncthreads per chunk; prefetch of kc+1 overlaps the whole kc body.
#define SKH_STRIDE 136
#define SK_BUF_H   (64 * SKH_STRIDE)    // 8704 halves
#define SVH_STRIDE 72
#define SV_BUF_H   (128 * SVH_STRIDE)   // 9216 halves
#define SM_V_H     (2 * SK_BUF_H)
#define ATTN_SMEM  ((SM_V_H + 2 * SV_BUF_H) * 2)   // 71680 B

__global__ void __launch_bounds__(128, 2) attn_mma_kernel() {
    extern __shared__ __half smh[];
    __half* sK  = smh;
    __half* sVt = smh + SM_V_H;
    const uint32_t sKa  = smem_u32(sK);
    const uint32_t sVta = smem_u32(sVt);

    const int tid  = threadIdx.x;
    const int warp = tid >> 5;
    const int lane = tid & 31;
    const int gr   = lane >> 2;
    const int tg   = lane & 3;
    const int b    = blockIdx.y;
    const int q0   = blockIdx.x * 64;
    const int qrow = warp * 16;

    const __half* qb = g_qh + (size_t)(b * NQ_B + q0 + qrow) * HID;
    uint32_t qf[8][4];
#pragma unroll
    for (int ks = 0; ks < 8; ks++) {
        qf[ks][0] = *(const uint32_t*)(qb + (size_t)gr * HID + ks * 16 + 2 * tg);
        qf[ks][1] = *(const uint32_t*)(qb + (size_t)(gr + 8) * HID + ks * 16 + 2 * tg);
        qf[ks][2] = *(const uint32_t*)(qb + (size_t)gr * HID + ks * 16 + 2 * tg + 8);
        qf[ks][3] = *(const uint32_t*)(qb + (size_t)(gr + 8) * HID + ks * 16 + 2 * tg + 8);
    }

    const __half* kb0 = g_kh + (size_t)(b * NK_B) * HID;
    const __half* vb0 = g_vTh + (size_t)(b * HID) * NK_B;

    // prefetch chunk 0 (K + V, one group)
#pragma unroll
    for (int i = 0; i < 8; i++) {
        int e = tid + i * 128;
        int row = e >> 4, c = e & 15;
        cpasync16(sKa + row * (SKH_STRIDE * 2) + c * 16, kb0 + (size_t)row * HID + c * 8);
    }
#pragma unroll
    for (int i = 0; i < 8; i++) {
        int e = tid + i * 128;
        int row = e >> 3, c = e & 7;
        cpasync16(sVta + row * (SVH_STRIDE * 2) + c * 16, vb0 + (size_t)row * NK_B + c * 8);
    }
    CP_COMMIT();

    float y[16][4];
#pragma unroll
    for (int nt = 0; nt < 16; nt++)
#pragma unroll
        for (int j = 0; j < 4; j++) y[nt][j] = 0.f;
    float m0 = -INFINITY, m1 = -INFINITY;
    float lsum0 = 0.f, lsum1 = 0.f;

    for (int kc = 0; kc < 49; kc++) {
        CP_WAIT(0);          // chunk kc landed (sole pending group)
        __syncthreads();     // all warps done with the buffers we overwrite next

        if (kc < 48) {       // prefetch kc+1 into the other buffers, one group
            const __half* kb = kb0 + (size_t)((kc + 1) * 64) * HID;
            const __half* vb = vb0 + (kc + 1) * 64;
            uint32_t kdst = sKa + ((kc + 1) & 1) * (SK_BUF_H * 2);
            uint32_t vdst = sVta + ((kc + 1) & 1) * (SV_BUF_H * 2);
#pragma unroll
            for (int i = 0; i < 8; i++) {
                int e = tid + i * 128;
                int row = e >> 4, c = e & 15;
                cpasync16(kdst + row * (SKH_STRIDE * 2) + c * 16, kb + (size_t)row * HID + c * 8);
            }
#pragma unroll
            for (int i = 0; i < 8; i++) {
                int e = tid + i * 128;
                int row = e >> 3, c = e & 7;
                cpasync16(vdst + row * (SVH_STRIDE * 2) + c * 16, vb + (size_t)row * NK_B + c * 8);
            }
            CP_COMMIT();
        }

        const __half* sKb = sK + (kc & 1) * SK_BUF_H;
        const __half* sVb = sVt + (kc & 1) * SV_BUF_H;

        // ---- S = Q K^T ----
        float s[8][4];
#pragma unroll
        for (int nt = 0; nt < 8; nt++)
#pragma unroll
            for (int j = 0; j < 4; j++) s[nt][j] = 0.f;
#pragma unroll
        for (int ks = 0; ks < 8; ks++) {
#pragma unroll
            for (int nt = 0; nt < 8; nt++) {
                uint32_t b0 = *(const uint32_t*)&sKb[(nt * 8 + gr) * SKH_STRIDE + ks * 16 + 2 * tg];
                uint32_t b1 = *(const uint32_t*)&sKb[(nt * 8 + gr) * SKH_STRIDE + ks * 16 + 2 * tg + 8];
                mma_f16(s[nt][0], s[nt][1], s[nt][2], s[nt][3],
                        qf[ks][0], qf[ks][1], qf[ks][2], qf[ks][3], b0, b1);
            }
        }

        // ---- running row max, rescale, exp, pack P ----
        float mx0 = -INFINITY, mx1 = -INFINITY;
#pragma unroll
        for (int nt = 0; nt < 8; nt++) {
            mx0 = fmaxf(mx0, fmaxf(s[nt][0], s[nt][1]));
            mx1 = fmaxf(mx1, fmaxf(s[nt][2], s[nt][3]));
        }
        mx0 = fmaxf(mx0, __shfl_xor_sync(0xffffffffu, mx0, 1));
        mx0 = fmaxf(mx0, __shfl_xor_sync(0xffffffffu, mx0, 2));
        mx1 = fmaxf(mx1, __shfl_xor_sync(0xffffffffu, mx1, 1));
        mx1 = fmaxf(mx1, __shfl_xor_sync(0xffffffffu, mx1, 2));
        float mn0 = fmaxf(m0, mx0);
        float mn1 = fmaxf(m1, mx1);
        float corr0 = __expf(m0 - mn0);
        float corr1 = __expf(m1 - mn1);
        m0 = mn0; m1 = mn1;
        lsum0 *= corr0; lsum1 *= corr1;
#pragma unroll
        for (int nt = 0; nt < 16; nt++) {
            y[nt][0] *= corr0; y[nt][1] *= corr0;
            y[nt][2] *= corr1; y[nt][3] *= corr1;
        }

        uint32_t pa[4][4];
#pragma unroll
        for (int nt = 0; nt < 8; nt++) {
            float p0 = __expf(s[nt][0] - m0);
            float p1 = __expf(s[nt][1] - m0);
            float p2 = __expf(s[nt][2] - m1);
            float p3 = __expf(s[nt][3] - m1);
            lsum0 += p0 + p1;
            lsum1 += p2 + p3;
            __half2 h01 = __floats2half2_rn(p0, p1);
            __half2 h23 = __floats2half2_rn(p2, p3);
            int kp = nt >> 1;
            if ((nt & 1) == 0) { pa[kp][0] = *(uint32_t*)&h01; pa[kp][1] = *(uint32_t*)&h23; }
            else               { pa[kp][2] = *(uint32_t*)&h01; pa[kp][3] = *(uint32_t*)&h23; }
        }

        // ---- Y += P V ----
#pragma unroll
        for (int ks = 0; ks < 4; ks++) {
#pragma unroll
            for (int nt = 0; nt < 16; nt++) {
                uint32_t b0 = *(const uint32_t*)&sVb[(nt * 8 + gr) * SVH_STRIDE + ks * 16 + 2 * tg];
                uint32_t b1 = *(const uint32_t*)&sVb[(nt * 8 + gr) * SVH_STRIDE + ks * 16 + 2 * tg + 8];
                mma_f16(y[nt][0], y[nt][1], y[nt][2], y[nt][3],
                        pa[ks][0], pa[ks][1], pa[ks][2], pa[ks][3], b0, b1);
            }
        }
    }

#pragma unroll
    for (int off = 1; off < 4; off <<= 1) {
        lsum0 += __shfl_xor_sync(0xffffffffu, lsum0, off);
        lsum1 += __shfl_xor_sync(0xffffffffu, lsum1, off);
    }
    const float inv0 = 1.0f / lsum0;
    const float inv1 = 1.0f / lsum1;

    __half* y0 = g_yh + (size_t)(b * NQ_B + q0 + qrow + gr) * HID;
    __half* y1 = g_yh + (size_t)(b * NQ_B + q0 + qrow + gr + 8) * HID;
#pragma unroll
    for (int nt = 0; nt < 16; nt++) {
        *(__half2*)(y0 + nt * 8 + 2 * tg) = __floats2half2_rn(y[nt][0] * inv0, y[nt][1] * inv0);
        *(__half2*)(y1 + nt * 8 + 2 * tg) = __floats2half2_rn(y[nt][2] * inv1, y[nt][3] * inv1);
    }
}

// ---------------- epilogue GEMM: out = rois + Y*wre^T + bre (fp16 HMMA) --------
#define EP_ASTRIDE 136
#define EP_DSTRIDE 129
#define EP_SMEM (128 * EP_DSTRIDE * 4)

__global__ void __launch_bounds__(256, 2) ep_mma(const float* __restrict__ rois,
                                                 const float* __restrict__ bre,
                                                 float* __restrict__ out) {
    extern __shared__ char esm[];
    __half* sA = (__half*)esm;
    float*  sD = (float*)esm;
    const uint32_t sAa = smem_u32(sA);

    const int tid  = threadIdx.x;
    const int warp = tid >> 5;
    const int lane = tid & 31;
    const int gr   = lane >> 2;
    const int tg   = lane & 3;
    const int m0   = blockIdx.x * 128;
    const int n0   = blockIdx.y * 128;
    const int qrow = warp * 16;

    {
        const __half* src = g_yh + (size_t)m0 * HID;
#pragma unroll
        for (int i = 0; i < 8; i++) {
            int e = tid + i * 256;
            int row = e >> 4, seg = e & 15;
            cpasync16(sAa + (row * EP_ASTRIDE + seg * 8) * 2, src + (size_t)row * HID + seg * 8);
        }
        CP_COMMIT();
        CP_WAIT(0);
        __syncthreads();
    }

    float y[16][4];
#pragma unroll
    for (int nt = 0; nt < 16; nt++)
#pragma unroll
        for (int j = 0; j < 4; j++) y[nt][j] = 0.f;

#pragma unroll
    for (int ks = 0; ks < 8; ks++) {
        int k = ks * 16;
        uint32_t a0 = *(const uint32_t*)&sA[(qrow + gr) * EP_ASTRIDE + k + 2 * tg];
        uint32_t a1 = *(const uint32_t*)&sA[(qrow + gr + 8) * EP_ASTRIDE + k + 2 * tg];
        uint32_t a2 = *(const uint32_t*)&sA[(qrow + gr) * EP_ASTRIDE + k + 2 * tg + 8];
        uint32_t a3 = *(const uint32_t*)&sA[(qrow + gr + 8) * EP_ASTRIDE + k + 2 * tg + 8];
#pragma unroll
        for (int nt = 0; nt < 16; nt++) {
            int o = n0 + nt * 8 + gr;
            uint32_t b0 = *(const uint32_t*)&g_wreh[(size_t)o * HID + k + 2 * tg];
            uint32_t b1 = *(const uint32_t*)&g_wreh[(size_t)o * HID + k + 2 * tg + 8];
            mma_f16(y[nt][0], y[nt][1], y[nt][2], y[nt][3], a0, a1, a2, a3, b0, b1);
        }
    }
    __syncthreads();

#pragma unroll
    for (int nt = 0; nt < 16; nt++) {
        int o = nt * 8 + 2 * tg;
        sD[(qrow + gr) * EP_DSTRIDE + o]         = y[nt][0];
        sD[(qrow + gr) * EP_DSTRIDE + o + 1]     = y[nt][1];
        sD[(qrow + gr + 8) * EP_DSTRIDE + o]     = y[nt][2];
        sD[(qrow + gr + 8) * EP_DSTRIDE + o + 1] = y[nt][3];
    }
    __syncthreads();

#pragma unroll 4
    for (int i = 0; i < 64; i++) {
        int e = tid + i * 256;
        int o = e >> 7, ml = e & 127;
        int m = m0 + ml;
        int n = m / HW;
        int p = m - n * HW;
        int co = n0 + o;
        size_t idx = (size_t)(n * C_IN + co) * HW + p;
        out[idx] = rois[idx] + sD[ml * EP_DSTRIDE + o] + bre[co];
    }
}

// ---------------- launch ------------------------------------------------------
extern "C" void kernel_launch(void* const* d_in, const int* in_sizes, int n_in,
                              void* d_out, int out_size) {
    const float* rois = (const float*)d_in[0];
    const float* wq  = (const float*)d_in[2];
    const float* bq  = (const float*)d_in[3];
    const float* wk  = (const float*)d_in[4];
    const float* bk  = (const float*)d_in[5];
    const float* wv  = (const float*)d_in[6];
    const float* bv  = (const float*)d_in[7];
    const float* wre = (const float*)d_in[8];
    const float* bre = (const float*)d_in[9];
    float* out = (float*)d_out;

    cudaFuncSetAttribute(attn_mma_kernel, cudaFuncAttributeMaxDynamicSharedMemorySize, ATTN_SMEM);
    cudaFuncSetAttribute(proj_mma, cudaFuncAttributeMaxDynamicSharedMemorySize, PJ_SMEM);
    cudaFuncSetAttribute(ep_mma, cudaFuncAttributeMaxDynamicSharedMemorySize, EP_SMEM);

    prep_weights_h<<<128, 256>>>(wq, wk, wv, wre);
    prep_rois<<<128, 256>>>(rois);
    proj_mma<<<294, 256, PJ_SMEM>>>(bq, bk, bv);
    attn_mma_kernel<<<dim3(196, 2), 128, ATTN_SMEM>>>();
    ep_mma<<<dim3(196, 2), 256, EP_SMEM>>>(rois, bre, out);
}